// round 12
// baseline (speedup 1.0000x reference)
#include <cuda_runtime.h>
#include <math.h>

#define BATCH 8192
#define SEQ 64
#define FEAT 65
#define KXG 68
#define HID 128
#define G3 384
#define DZ 64

typedef unsigned long long u64;

#define PK2(d, x)       asm("mov.b64 %0, {%1, %1};" : "=l"(d) : "f"(x))
#define FMA2(c, a, b)   asm("fma.rn.f32x2 %0, %1, %2, %0;" : "+l"(c) : "l"(a), "l"(b))
#define UPK2(lo, hi, s) asm("mov.b64 {%0, %1}, %2;" : "=f"(lo), "=f"(hi) : "l"(s))

// ---------------- scratch (device globals; no allocation allowed) ----------
__device__ float  d_HtH[BATCH*64*64];
__device__ float  d_Hty[BATCH*64];
__device__ double d_stats[128];
__device__ float  d_wsum[2*G3];
__device__ float  d_xg[402653184];               // (2*SEQ*BATCH*G3)
__device__ float  d_h[2][2*BATCH*HID];
__device__ float  d_go[134217728];               // (BATCH*SEQ*256)
__device__ float  d_wx[BATCH*SEQ*DZ];
__device__ float  d_gx[BATCH*256];
__device__ float  d_wih_t[2*KXG*G3];
__device__ float  d_whh_t[2*HID*G3];
__device__ float  d_wxt[256*DZ];

// ---------------- init + weight prep + wsum ----------------------------------
__global__ __launch_bounds__(256) void k_init(const float* __restrict__ wih,
                                              const float* __restrict__ whh,
                                              const float* __restrict__ wx) {
    int idx = blockIdx.x*256 + threadIdx.x;
    if (idx < 2*BATCH*HID) d_h[0][idx] = 0.f;
    if (blockIdx.x == 0 && threadIdx.x < 128) d_stats[threadIdx.x] = 0.0;
    if (idx < 2*KXG*G3) {
        int g = idx % G3; int rest = idx / G3;
        int f = rest % KXG; int dir = rest / KXG;
        d_wih_t[idx] = (f < FEAT) ? wih[((size_t)dir*G3 + g)*FEAT + f] : 0.f;
    }
    if (idx < 2*HID*G3) {
        int g = idx % G3; int rest = idx / G3;
        int k = rest % HID; int dir = rest / HID;
        d_whh_t[idx] = whh[((size_t)dir*G3 + g)*HID + k];
    }
    if (idx < 256*DZ) {
        int n = idx & 63, k = idx >> 6;
        d_wxt[idx] = wx[n*256 + k];
    }
    if (idx < 2*G3) {
        float s = 0.f;
        const float* w = wih + idx*FEAT;
        for (int f=0; f<FEAT; f++) s += w[f];
        d_wsum[idx] = s;
    }
}

// ---------------- per-batch HtH, Hty + BN partial stats (f32x2) --------------
__global__ __launch_bounds__(256) void k_hth(const float* __restrict__ Hg,
                                             const float* __restrict__ yg) {
    int b = blockIdx.x;
    __shared__ __align__(16) float Hs[64][68];
    __shared__ float ys[64], hty[64], csum[64], csq[64];
    int tid = threadIdx.x;
    const float* Hb = Hg + (size_t)b*4096;
    for (int i = tid; i < 4096; i += 256) Hs[i>>6][i&63] = Hb[i];
    if (tid < 64) { ys[tid] = yg[b*64+tid]; csum[tid]=0.f; csq[tid]=0.f; }
    __syncthreads();
    if (tid < 64) {
        float a = 0.f;
#pragma unroll
        for (int r=0;r<64;r++) a += Hs[r][tid]*ys[r];
        hty[tid] = a;
        d_Hty[b*64+tid] = a;
    }
    int ty = tid >> 4, tx = tid & 15;
    u64 acc[4][2] = {};
#pragma unroll 8
    for (int r = 0; r < 64; r++) {
        float4 a = *(const float4*)&Hs[r][ty*4];
        ulonglong2 bb = *(const ulonglong2*)&Hs[r][tx*4];
        u64 aa;
        PK2(aa, a.x); FMA2(acc[0][0], aa, bb.x); FMA2(acc[0][1], aa, bb.y);
        PK2(aa, a.y); FMA2(acc[1][0], aa, bb.x); FMA2(acc[1][1], aa, bb.y);
        PK2(aa, a.z); FMA2(acc[2][0], aa, bb.x); FMA2(acc[2][1], aa, bb.y);
        PK2(aa, a.w); FMA2(acc[3][0], aa, bb.x); FMA2(acc[3][1], aa, bb.y);
    }
    float* outp = d_HtH + (size_t)b*4096;
#pragma unroll
    for (int i=0;i<4;i++) {
        float4 v;
        UPK2(v.x, v.y, acc[i][0]);
        UPK2(v.z, v.w, acc[i][1]);
        *reinterpret_cast<float4*>(&outp[(ty*4+i)*64 + tx*4]) = v;
        float s1 = v.x+v.y+v.z+v.w;
        float s2 = v.x*v.x+v.y*v.y+v.z*v.z+v.w*v.w;
        atomicAdd(&csum[ty*4+i], s1);
        atomicAdd(&csq[ty*4+i],  s2);
    }
    __syncthreads();
    if (tid < 64) {
        float v = hty[tid];
        atomicAdd(&d_stats[tid],    (double)(csum[tid]+v));
        atomicAdd(&d_stats[64+tid], (double)(csq[tid]+v*v));
    }
}

// ---------------- GRU input gates: dup-A layout, BN folded in-block ----------
// smem: As2[68][128] float2 (69632 B) + Bs[68][132] float (35904 B)
#define XG_SMEM (KXG*128*8 + KXG*132*4)
__global__ __launch_bounds__(256,2) void k_xg(const float* __restrict__ bih,
                                              const float* __restrict__ gamma,
                                              const float* __restrict__ beta) {
    extern __shared__ __align__(16) char xraw_s[];
    float2 (*As2)[128] = (float2(*)[128])xraw_s;
    float  (*Bs)[132]  = (float(*)[132])(xraw_s + KXG*128*8);
    __shared__ float sc_s, sh_s;
    int n0 = blockIdx.x*128, b0 = blockIdx.y*128;
    int z = blockIdx.z, dir = z >> 6, s = z & 63;
    int tid = threadIdx.x;
    if (tid == 0) {
        double n  = (double)BATCH*FEAT;
        double mu = d_stats[s]/n;
        double var = d_stats[64+s]/n - mu*mu;
        double scd = (double)gamma[s] / sqrt(var + 1e-5);
        sc_s = (float)scd;
        sh_s = beta[s] - (float)(mu*scd);
    }
    for (int i = tid; i < 128*16; i += 256) {
        int m = i >> 4, f4 = (i & 15)*4;
        float4 v = *(const float4*)&d_HtH[(size_t)(b0+m)*4096 + s*64 + f4];
        As2[f4+0][m] = make_float2(v.x, v.x);
        As2[f4+1][m] = make_float2(v.y, v.y);
        As2[f4+2][m] = make_float2(v.z, v.z);
        As2[f4+3][m] = make_float2(v.w, v.w);
    }
    if (tid < 128) {
        float hv = d_Hty[(b0+tid)*64 + s];
        As2[64][tid] = make_float2(hv, hv);
        As2[65][tid] = make_float2(0.f, 0.f);
        As2[66][tid] = make_float2(0.f, 0.f);
        As2[67][tid] = make_float2(0.f, 0.f);
    }
    for (int i = tid; i < KXG*32; i += 256) {
        int f = i >> 5, n4 = (i & 31)*4;
        *(float4*)&Bs[f][n4] =
            *(const float4*)&d_wih_t[((size_t)dir*KXG + f)*G3 + n0 + n4];
    }
    __syncthreads();
    int ty = tid >> 4, tx = tid & 15;
    u64 acc[8][4] = {};
#pragma unroll 4
    for (int k = 0; k < KXG; k++) {
        u64 a[8];
#pragma unroll
        for (int i=0;i<8;i++) a[i] = *(const u64*)&As2[k][ty*8+i];
        ulonglong2 b0v = *(const ulonglong2*)&Bs[k][tx*8];
        ulonglong2 b1v = *(const ulonglong2*)&Bs[k][tx*8+4];
#pragma unroll
        for (int i=0;i<8;i++) {
            FMA2(acc[i][0], a[i], b0v.x); FMA2(acc[i][1], a[i], b0v.y);
            FMA2(acc[i][2], a[i], b1v.x); FMA2(acc[i][3], a[i], b1v.y);
        }
    }
    float sc = sc_s, sh = sh_s;
    int gn = n0 + tx*8;
    float wv[8];
#pragma unroll
    for (int j=0;j<8;j++) wv[j] = sh*d_wsum[dir*G3+gn+j] + bih[dir*G3+gn+j];
    size_t zb = ((size_t)z*BATCH + b0)*G3;
#pragma unroll
    for (int i=0;i<8;i++) {
        int m = ty*8 + i;
        float o[8];
#pragma unroll
        for (int j=0;j<4;j++) {
            float lo, hi; UPK2(lo, hi, acc[i][j]);
            o[2*j]   = lo*sc + wv[2*j];
            o[2*j+1] = hi*sc + wv[2*j+1];
        }
        *(float4*)&d_xg[zb + (size_t)m*G3 + gn]     = make_float4(o[0],o[1],o[2],o[3]);
        *(float4*)&d_xg[zb + (size_t)m*G3 + gn + 4] = make_float4(o[4],o[5],o[6],o[7]);
    }
}

// ---------------- FUSED GRU step: dup-A, no inner-loop MOVs -------------------
__global__ __launch_bounds__(256,2) void k_gru_step(const float* __restrict__ bhh,
                                                    int step, int ping) {
    __shared__ __align__(16) float2 As2[32][36];   // [k][m-dup] 9216 B
    __shared__ __align__(16) float  Bs[32][388];   // [k][gatecol]
    int dir = blockIdx.y, b0 = blockIdx.x*32;
    int sx = dir ? (63 - step) : step;
    int tid = threadIdx.x, ty = tid >> 6, tx = tid & 63;
    const float* hp = d_h[ping] + (size_t)dir*BATCH*HID;
    const float* wt = d_whh_t + (size_t)dir*HID*G3;
    u64 acc[8][3] = {};
    int fm = tid >> 3, fk4 = (tid & 7)*4;
    for (int kc = 0; kc < 4; kc++) {
        __syncthreads();
        {
            float4 v = *(const float4*)&hp[(size_t)(b0+fm)*HID + kc*32 + fk4];
            As2[fk4+0][fm] = make_float2(v.x, v.x);
            As2[fk4+1][fm] = make_float2(v.y, v.y);
            As2[fk4+2][fm] = make_float2(v.z, v.z);
            As2[fk4+3][fm] = make_float2(v.w, v.w);
        }
#pragma unroll
        for (int p = 0; p < 12; p++) {
            int i = p*256 + tid;
            int k = i / 96, n4 = (i - k*96)*4;
            *(float4*)&Bs[k][n4] =
                *(const float4*)&wt[(size_t)(kc*32+k)*G3 + n4];
        }
        __syncthreads();
#pragma unroll 4
        for (int k = 0; k < 32; k++) {
            u64 a[8];
#pragma unroll
            for (int i=0;i<8;i++) a[i] = *(const u64*)&As2[k][ty*8+i];
            u64 br = *(const u64*)&Bs[k][tx*2];
            u64 bz = *(const u64*)&Bs[k][128 + tx*2];
            u64 bn = *(const u64*)&Bs[k][256 + tx*2];
#pragma unroll
            for (int i=0;i<8;i++) {
                FMA2(acc[i][0], a[i], br);
                FMA2(acc[i][1], a[i], bz);
                FMA2(acc[i][2], a[i], bn);
            }
        }
    }
    int j0 = tx*2;
    const float* bh = bhh + dir*G3;
    float2 bhr = *(const float2*)&bh[j0];
    float2 bhz = *(const float2*)&bh[128 + j0];
    float2 bhn = *(const float2*)&bh[256 + j0];
    size_t xzb = ((size_t)(dir*64 + sx)*BATCH + b0)*G3;
    float* hout = d_h[1-ping] + (size_t)dir*BATCH*HID;
#pragma unroll
    for (int i = 0; i < 8; i++) {
        int m = ty*8 + i, b = b0 + m;
        const float* xgp = &d_xg[xzb + (size_t)m*G3];
        float2 xr = *(const float2*)&xgp[j0];
        float2 xz = *(const float2*)&xgp[128 + j0];
        float2 xn = *(const float2*)&xgp[256 + j0];
        float2 hpv = *(const float2*)&hp[(size_t)b*HID + j0];
        float hr0,hr1,hz0,hz1,hn0,hn1;
        UPK2(hr0,hr1,acc[i][0]); UPK2(hz0,hz1,acc[i][1]); UPK2(hn0,hn1,acc[i][2]);
        float r0 = 1.f/(1.f + expf(-(xr.x + hr0 + bhr.x)));
        float r1 = 1.f/(1.f + expf(-(xr.y + hr1 + bhr.y)));
        float z0 = 1.f/(1.f + expf(-(xz.x + hz0 + bhz.x)));
        float z1 = 1.f/(1.f + expf(-(xz.y + hz1 + bhz.y)));
        float n0 = tanhf(xn.x + r0*(hn0 + bhn.x));
        float n1 = tanhf(xn.y + r1*(hn1 + bhn.y));
        float h0 = (1.f - z0)*n0 + z0*hpv.x;
        float h1 = (1.f - z1)*n1 + z1*hpv.y;
        *(float2*)&hout[(size_t)b*HID + j0] = make_float2(h0, h1);
        *(float2*)&d_go[((size_t)b*64 + sx)*256 + dir*128 + j0] = make_float2(h0, h1);
    }
}

// ---------------- w_x = go @ Wx^T: dup-A 256x64 tile --------------------------
#define WX_SMEM (32*256*8 + 32*68*4)
__global__ __launch_bounds__(256,2) void k_wx() {
    extern __shared__ __align__(16) char wraw_s[];
    float2 (*As2)[256] = (float2(*)[256])wraw_s;
    float  (*Bs)[68]   = (float(*)[68])(wraw_s + 32*256*8);
    int m0 = blockIdx.x*256;
    int tid = threadIdx.x, ty = tid >> 3, tx = tid & 7;
    u64 acc[8][4] = {};
    for (int kc = 0; kc < 8; kc++) {
        __syncthreads();
#pragma unroll
        for (int p = 0; p < 8; p++) {
            int i = p*256 + tid;
            int m = i >> 3, k4 = (i & 7)*4;
            float4 v = *(const float4*)&d_go[(size_t)(m0+m)*256 + kc*32 + k4];
            As2[k4+0][m] = make_float2(v.x, v.x);
            As2[k4+1][m] = make_float2(v.y, v.y);
            As2[k4+2][m] = make_float2(v.z, v.z);
            As2[k4+3][m] = make_float2(v.w, v.w);
        }
        for (int i = tid; i < 32*16; i += 256) {
            int k = i >> 4, n4 = (i & 15)*4;
            *(float4*)&Bs[k][n4] = *(const float4*)&d_wxt[(size_t)(kc*32+k)*64 + n4];
        }
        __syncthreads();
#pragma unroll 4
        for (int k = 0; k < 32; k++) {
            u64 a[8];
#pragma unroll
            for (int i=0;i<8;i++) a[i] = *(const u64*)&As2[k][ty*8+i];
            ulonglong2 b0v = *(const ulonglong2*)&Bs[k][tx*8];
            ulonglong2 b1v = *(const ulonglong2*)&Bs[k][tx*8+4];
#pragma unroll
            for (int i=0;i<8;i++) {
                FMA2(acc[i][0], a[i], b0v.x); FMA2(acc[i][1], a[i], b0v.y);
                FMA2(acc[i][2], a[i], b1v.x); FMA2(acc[i][3], a[i], b1v.y);
            }
        }
    }
#pragma unroll
    for (int i=0;i<8;i++) {
        int m = m0 + ty*8 + i;
        float o[8];
#pragma unroll
        for (int j=0;j<4;j++) UPK2(o[2*j], o[2*j+1], acc[i][j]);
        *(float4*)&d_wx[(size_t)m*64 + tx*8]     = make_float4(o[0],o[1],o[2],o[3]);
        *(float4*)&d_wx[(size_t)m*64 + tx*8 + 4] = make_float4(o[4],o[5],o[6],o[7]);
    }
}

// ---------------- gx[b,c] = sum_s go[b,s,c] * xhat[b,s] -----------------------
__global__ __launch_bounds__(256) void k_gx(const float* __restrict__ x_raw) {
    int b = blockIdx.x;
    int c = threadIdx.x;
    __shared__ float xh[64];
    if (c < 64) xh[c] = 2.f*x_raw[b*64+c] - 3.f;
    __syncthreads();
    float acc = 0.f;
    const float* g = d_go + (size_t)b*64*256;
#pragma unroll 8
    for (int s=0;s<64;s++) acc += g[s*256+c]*xh[s];
    d_gx[(size_t)b*256 + c] = acc;
}

// ---------------- final per-batch (round-9 serial form) -----------------------
__global__ __launch_bounds__(256) void k_final(const float* __restrict__ Wz,
                                               float* __restrict__ outp) {
    int b = blockIdx.x, tid = threadIdx.x;
    __shared__ float Ws[64][65];
    __shared__ float As[64][65];
    __shared__ float hy[64], zv[64], wh[64], t1[64], t2[64];
    __shared__ float gxs[256];
    for (int i=tid;i<4096;i+=256) Ws[i>>6][i&63] = d_wx[(size_t)b*4096 + i];
    for (int i=tid;i<4096;i+=256) As[i>>6][i&63] = d_HtH[(size_t)b*4096 + i];
    if (tid<64) hy[tid] = d_Hty[b*64+tid];
    gxs[tid] = d_gx[(size_t)b*256 + tid];
    __syncthreads();
    if (tid<64) {
        float a=0.f;
        const float* wz = Wz + tid*256;
#pragma unroll 8
        for (int c=0;c<256;c++) a += wz[c]*gxs[c];
        zv[tid] = a;
        float w=0.f;
#pragma unroll
        for (int s=0;s<64;s++) w += Ws[s][tid]*hy[s];
        wh[tid] = w;
    }
    __syncthreads();
    for (int it=0; it<10; it++) {
        if (tid<64) { float a=0.f;
#pragma unroll
            for (int zc=0;zc<64;zc++) a += Ws[tid][zc]*zv[zc];
            t1[tid]=a; }
        __syncthreads();
        if (tid<64) { float a=0.f;
#pragma unroll
            for (int u=0;u<64;u++) a += As[tid][u]*t1[u];
            t2[tid]=a; }
        __syncthreads();
        if (tid<64) { float a=0.f;
#pragma unroll
            for (int s=0;s<64;s++) a += Ws[s][tid]*t2[s];
            zv[tid] += 2e-6f*(wh[tid]-a); }
        __syncthreads();
    }
    if (tid<64) {
        float a=0.f;
#pragma unroll
        for (int zc=0;zc<64;zc++) a += Ws[tid][zc]*zv[zc];
        outp[b*64+tid] = a;
    }
}

// ---------------- launch -------------------------------------------------------
extern "C" void kernel_launch(void* const* d_in, const int* in_sizes, int n_in,
                              void* d_out, int out_size) {
    const float* y     = (const float*)d_in[0];
    const float* H     = (const float*)d_in[1];
    const float* xraw  = (const float*)d_in[2];
    const float* wih   = (const float*)d_in[3];
    const float* whh   = (const float*)d_in[4];
    const float* bih   = (const float*)d_in[5];
    const float* bhh   = (const float*)d_in[6];
    const float* Wz    = (const float*)d_in[7];
    const float* Wx    = (const float*)d_in[8];
    const float* gamma = (const float*)d_in[9];
    const float* beta  = (const float*)d_in[10];
    float* outp = (float*)d_out;

    cudaFuncSetAttribute(k_xg, cudaFuncAttributeMaxDynamicSharedMemorySize, XG_SMEM);
    cudaFuncSetAttribute(k_wx, cudaFuncAttributeMaxDynamicSharedMemorySize, WX_SMEM);

    k_init<<<8192,256>>>(wih, whh, Wx);              // slot 0
    k_hth<<<BATCH,256>>>(H, y);                      // slot 1
    k_xg<<<dim3(3,64,128),256,XG_SMEM>>>(bih, gamma, beta);   // slot 2
    for (int step=0; step<64; step++) {              // slot 3 = gru step 0 (profiled)
        k_gru_step<<<dim3(256,2),256>>>(bhh, step, step & 1);
    }
    k_wx<<<2048,256,WX_SMEM>>>();
    k_gx<<<BATCH,256>>>(xraw);
    k_final<<<BATCH,256>>>(Wz, outp);
}

// round 13
// speedup vs baseline: 1.1816x; 1.1816x over previous
#include <cuda_runtime.h>
#include <math.h>

#define BATCH 8192
#define SEQ 64
#define FEAT 65
#define KXG 68
#define HID 128
#define G3 384
#define DZ 64

typedef unsigned long long u64;

// ---------------- packed fp32x2 FMA (FFMA2) ---------------------------------
#define PK2(d, x)       asm("mov.b64 %0, {%1, %1};" : "=l"(d) : "f"(x))
#define FMA2(c, a, b)   asm("fma.rn.f32x2 %0, %1, %2, %0;" : "+l"(c) : "l"(a), "l"(b))
#define UPK2(lo, hi, s) asm("mov.b64 {%0, %1}, %2;" : "=f"(lo), "=f"(hi) : "l"(s))

#define ROW8(acc_i, av)  { u64 aa_; PK2(aa_, av); \
    FMA2(acc_i[0], aa_, b0.x); FMA2(acc_i[1], aa_, b0.y); \
    FMA2(acc_i[2], aa_, b1.x); FMA2(acc_i[3], aa_, b1.y); }

// ---------------- scratch (device globals; no allocation allowed) ----------
__device__ float  d_HtH[BATCH*64*64];
__device__ float  d_Hty[BATCH*64];
__device__ double d_stats[128];
__device__ float  d_scale[64];
__device__ float  d_shift[64];
__device__ float  d_wsum[2*G3];
__device__ float  d_xg[402653184];               // (2*SEQ*BATCH*G3)
__device__ float  d_h[2][2*BATCH*HID];
__device__ float  d_go[134217728];               // (BATCH*SEQ*256)
__device__ float  d_wx[BATCH*SEQ*DZ];
__device__ float  d_gx[BATCH*256];
__device__ float  d_wih_t[2*KXG*G3];
__device__ float  d_whh_t[2*HID*G3];
__device__ float  d_wxt[256*DZ];

// ---------------- init -------------------------------------------------------
__global__ __launch_bounds__(256) void k_init() {
    int idx = blockIdx.x*256 + threadIdx.x;
    if (idx < 2*BATCH*HID) d_h[0][idx] = 0.f;
    if (blockIdx.x == 0 && threadIdx.x < 128) d_stats[threadIdx.x] = 0.0;
}

// ---------------- weight prep: transpose to k-major --------------------------
__global__ __launch_bounds__(256) void k_prep(const float* __restrict__ wih,
                                              const float* __restrict__ whh,
                                              const float* __restrict__ wx) {
    int idx = blockIdx.x*256 + threadIdx.x;
    if (idx < 2*KXG*G3) {
        int g = idx % G3; int rest = idx / G3;
        int f = rest % KXG; int dir = rest / KXG;
        d_wih_t[idx] = (f < FEAT) ? wih[((size_t)dir*G3 + g)*FEAT + f] : 0.f;
    }
    if (idx < 2*HID*G3) {
        int g = idx % G3; int rest = idx / G3;
        int k = rest % HID; int dir = rest / HID;
        d_whh_t[idx] = whh[((size_t)dir*G3 + g)*HID + k];
    }
    if (idx < 256*DZ) {
        int n = idx & 63, k = idx >> 6;
        d_wxt[idx] = wx[n*256 + k];
    }
}

// ---------------- per-batch HtH, Hty + BN partial stats (f32x2) --------------
__global__ __launch_bounds__(256) void k_hth(const float* __restrict__ Hg,
                                             const float* __restrict__ yg) {
    int b = blockIdx.x;
    __shared__ __align__(16) float Hs[64][68];
    __shared__ float ys[64], hty[64], csum[64], csq[64];
    int tid = threadIdx.x;
    const float* Hb = Hg + (size_t)b*4096;
    for (int i = tid; i < 4096; i += 256) Hs[i>>6][i&63] = Hb[i];
    if (tid < 64) { ys[tid] = yg[b*64+tid]; csum[tid]=0.f; csq[tid]=0.f; }
    __syncthreads();
    if (tid < 64) {
        float a = 0.f;
#pragma unroll
        for (int r=0;r<64;r++) a += Hs[r][tid]*ys[r];
        hty[tid] = a;
        d_Hty[b*64+tid] = a;
    }
    int ty = tid >> 4, tx = tid & 15;
    u64 acc[4][2] = {};
#pragma unroll 8
    for (int r = 0; r < 64; r++) {
        float4 a = *(const float4*)&Hs[r][ty*4];
        ulonglong2 bb = *(const ulonglong2*)&Hs[r][tx*4];
        u64 aa;
        PK2(aa, a.x); FMA2(acc[0][0], aa, bb.x); FMA2(acc[0][1], aa, bb.y);
        PK2(aa, a.y); FMA2(acc[1][0], aa, bb.x); FMA2(acc[1][1], aa, bb.y);
        PK2(aa, a.z); FMA2(acc[2][0], aa, bb.x); FMA2(acc[2][1], aa, bb.y);
        PK2(aa, a.w); FMA2(acc[3][0], aa, bb.x); FMA2(acc[3][1], aa, bb.y);
    }
    float* outp = d_HtH + (size_t)b*4096;
#pragma unroll
    for (int i=0;i<4;i++) {
        float4 v;
        UPK2(v.x, v.y, acc[i][0]);
        UPK2(v.z, v.w, acc[i][1]);
        *reinterpret_cast<float4*>(&outp[(ty*4+i)*64 + tx*4]) = v;
        float s1 = v.x+v.y+v.z+v.w;
        float s2 = v.x*v.x+v.y*v.y+v.z*v.z+v.w*v.w;
        atomicAdd(&csum[ty*4+i], s1);
        atomicAdd(&csq[ty*4+i],  s2);
    }
    __syncthreads();
    if (tid < 64) {
        float v = hty[tid];
        atomicAdd(&d_stats[tid],    (double)(csum[tid]+v));
        atomicAdd(&d_stats[64+tid], (double)(csq[tid]+v*v));
    }
}

// ---------------- finalize BN scale/shift + W_ih row sums --------------------
__global__ void k_bn(const float* __restrict__ gamma, const float* __restrict__ beta,
                     const float* __restrict__ wih) {
    int tid = threadIdx.x;
    if (tid < 64) {
        double n  = (double)BATCH*FEAT;
        double mu = d_stats[tid]/n;
        double var = d_stats[64+tid]/n - mu*mu;
        double sc = (double)gamma[tid] / sqrt(var + 1e-5);
        d_scale[tid] = (float)sc;
        d_shift[tid] = beta[tid] - (float)(mu*sc);
    }
    if (tid < 2*G3) {
        float s = 0.f;
        const float* w = wih + tid*FEAT;
        for (int f=0; f<FEAT; f++) s += w[f];
        d_wsum[tid] = s;
    }
}

// ---------------- GRU input gates: 128x128 tile, f32x2 ------------------------
#define XG_SMEM (2*KXG*132*4)
__global__ __launch_bounds__(256,2) void k_xg(const float* __restrict__ bih) {
    extern __shared__ __align__(16) float xs[];
    float (*As)[132] = (float(*)[132])xs;
    float (*Bs)[132] = (float(*)[132])(xs + KXG*132);
    int n0 = blockIdx.x*128, b0 = blockIdx.y*128;
    int z = blockIdx.z, dir = z >> 6, s = z & 63;
    int tid = threadIdx.x;
    for (int i = tid; i < 128*16; i += 256) {
        int m = i >> 4, f4 = (i & 15)*4;
        float4 v = *(const float4*)&d_HtH[(size_t)(b0+m)*4096 + s*64 + f4];
        As[f4+0][m]=v.x; As[f4+1][m]=v.y; As[f4+2][m]=v.z; As[f4+3][m]=v.w;
    }
    if (tid < 128) {
        As[64][tid] = d_Hty[(b0+tid)*64 + s];
        As[65][tid] = 0.f; As[66][tid] = 0.f; As[67][tid] = 0.f;
    }
    for (int i = tid; i < KXG*32; i += 256) {
        int f = i >> 5, n4 = (i & 31)*4;
        *(float4*)&Bs[f][n4] =
            *(const float4*)&d_wih_t[((size_t)dir*KXG + f)*G3 + n0 + n4];
    }
    __syncthreads();
    int ty = tid >> 4, tx = tid & 15;
    u64 acc[8][4] = {};
#pragma unroll 4
    for (int k = 0; k < KXG; k++) {
        float4 a0 = *(const float4*)&As[k][ty*8];
        float4 a1 = *(const float4*)&As[k][ty*8+4];
        ulonglong2 b0 = *(const ulonglong2*)&Bs[k][tx*8];
        ulonglong2 b1 = *(const ulonglong2*)&Bs[k][tx*8+4];
        ROW8(acc[0], a0.x) ROW8(acc[1], a0.y) ROW8(acc[2], a0.z) ROW8(acc[3], a0.w)
        ROW8(acc[4], a1.x) ROW8(acc[5], a1.y) ROW8(acc[6], a1.z) ROW8(acc[7], a1.w)
    }
    float sc = d_scale[s], sh = d_shift[s];
    int gn = n0 + tx*8;
    float wv[8];
#pragma unroll
    for (int j=0;j<8;j++) wv[j] = sh*d_wsum[dir*G3+gn+j] + bih[dir*G3+gn+j];
    size_t zb = ((size_t)z*BATCH + b0)*G3;
#pragma unroll
    for (int i=0;i<8;i++) {
        int m = ty*8 + i;
        float o[8];
#pragma unroll
        for (int j=0;j<4;j++) {
            float lo, hi; UPK2(lo, hi, acc[i][j]);
            o[2*j]   = lo*sc + wv[2*j];
            o[2*j+1] = hi*sc + wv[2*j+1];
        }
        *(float4*)&d_xg[zb + (size_t)m*G3 + gn]     = make_float4(o[0],o[1],o[2],o[3]);
        *(float4*)&d_xg[zb + (size_t)m*G3 + gn + 4] = make_float4(o[4],o[5],o[6],o[7]);
    }
}

// ---------------- FUSED GRU step (round-9 winner + 3 CTAs/SM reg cap) ---------
__global__ __launch_bounds__(256,3) void k_gru_step(const float* __restrict__ bhh,
                                                    int step, int ping) {
    __shared__ __align__(16) float As[32][36];
    __shared__ __align__(16) float Bs[32][388];
    int dir = blockIdx.y, b0 = blockIdx.x*32;
    int sx = dir ? (63 - step) : step;
    int tid = threadIdx.x, ty = tid >> 6, tx = tid & 63;
    const float* hp = d_h[ping] + (size_t)dir*BATCH*HID;
    const float* wt = d_whh_t + (size_t)dir*HID*G3;
    u64 acc[8][3] = {};
    int fm = tid >> 3, fk4 = (tid & 7)*4;
    for (int kc = 0; kc < 4; kc++) {
        __syncthreads();
        {
            float4 v = *(const float4*)&hp[(size_t)(b0+fm)*HID + kc*32 + fk4];
            As[fk4+0][fm]=v.x; As[fk4+1][fm]=v.y; As[fk4+2][fm]=v.z; As[fk4+3][fm]=v.w;
        }
#pragma unroll
        for (int p = 0; p < 12; p++) {
            int i = p*256 + tid;
            int k = i / 96, n4 = (i - k*96)*4;
            *(float4*)&Bs[k][n4] =
                *(const float4*)&wt[(size_t)(kc*32+k)*G3 + n4];
        }
        __syncthreads();
#pragma unroll 4
        for (int k = 0; k < 32; k++) {
            float4 a0 = *(const float4*)&As[k][ty*8];
            float4 a1 = *(const float4*)&As[k][ty*8+4];
            u64 br = *(const u64*)&Bs[k][tx*2];
            u64 bz = *(const u64*)&Bs[k][128 + tx*2];
            u64 bn = *(const u64*)&Bs[k][256 + tx*2];
            u64 aa;
            PK2(aa, a0.x); FMA2(acc[0][0], aa, br); FMA2(acc[0][1], aa, bz); FMA2(acc[0][2], aa, bn);
            PK2(aa, a0.y); FMA2(acc[1][0], aa, br); FMA2(acc[1][1], aa, bz); FMA2(acc[1][2], aa, bn);
            PK2(aa, a0.z); FMA2(acc[2][0], aa, br); FMA2(acc[2][1], aa, bz); FMA2(acc[2][2], aa, bn);
            PK2(aa, a0.w); FMA2(acc[3][0], aa, br); FMA2(acc[3][1], aa, bz); FMA2(acc[3][2], aa, bn);
            PK2(aa, a1.x); FMA2(acc[4][0], aa, br); FMA2(acc[4][1], aa, bz); FMA2(acc[4][2], aa, bn);
            PK2(aa, a1.y); FMA2(acc[5][0], aa, br); FMA2(acc[5][1], aa, bz); FMA2(acc[5][2], aa, bn);
            PK2(aa, a1.z); FMA2(acc[6][0], aa, br); FMA2(acc[6][1], aa, bz); FMA2(acc[6][2], aa, bn);
            PK2(aa, a1.w); FMA2(acc[7][0], aa, br); FMA2(acc[7][1], aa, bz); FMA2(acc[7][2], aa, bn);
        }
    }
    int j0 = tx*2;
    const float* bh = bhh + dir*G3;
    float2 bhr = *(const float2*)&bh[j0];
    float2 bhz = *(const float2*)&bh[128 + j0];
    float2 bhn = *(const float2*)&bh[256 + j0];
    size_t xzb = ((size_t)(dir*64 + sx)*BATCH + b0)*G3;
    float* hout = d_h[1-ping] + (size_t)dir*BATCH*HID;
#pragma unroll
    for (int i = 0; i < 8; i++) {
        int m = ty*8 + i, b = b0 + m;
        const float* xgp = &d_xg[xzb + (size_t)m*G3];
        float2 xr = *(const float2*)&xgp[j0];
        float2 xz = *(const float2*)&xgp[128 + j0];
        float2 xn = *(const float2*)&xgp[256 + j0];
        float2 hpv = *(const float2*)&hp[(size_t)b*HID + j0];
        float hr0,hr1,hz0,hz1,hn0,hn1;
        UPK2(hr0,hr1,acc[i][0]); UPK2(hz0,hz1,acc[i][1]); UPK2(hn0,hn1,acc[i][2]);
        float r0 = 1.f/(1.f + expf(-(xr.x + hr0 + bhr.x)));
        float r1 = 1.f/(1.f + expf(-(xr.y + hr1 + bhr.y)));
        float z0 = 1.f/(1.f + expf(-(xz.x + hz0 + bhz.x)));
        float z1 = 1.f/(1.f + expf(-(xz.y + hz1 + bhz.y)));
        float n0 = tanhf(xn.x + r0*(hn0 + bhn.x));
        float n1 = tanhf(xn.y + r1*(hn1 + bhn.y));
        float h0 = (1.f - z0)*n0 + z0*hpv.x;
        float h1 = (1.f - z1)*n1 + z1*hpv.y;
        *(float2*)&hout[(size_t)b*HID + j0] = make_float2(h0, h1);
        *(float2*)&d_go[((size_t)b*64 + sx)*256 + dir*128 + j0] = make_float2(h0, h1);
    }
}

// ---------------- w_x = go @ Wx^T: 256x64 tile, f32x2 -------------------------
__global__ __launch_bounds__(256,2) void k_wx() {
    __shared__ __align__(16) float As[32][260];
    __shared__ __align__(16) float Bs[32][68];
    int m0 = blockIdx.x*256;
    int tid = threadIdx.x, ty = tid >> 3, tx = tid & 7;
    u64 acc[8][4] = {};
    for (int kc = 0; kc < 8; kc++) {
        __syncthreads();
#pragma unroll
        for (int p = 0; p < 8; p++) {
            int i = p*256 + tid;
            int m = i >> 3, k4 = (i & 7)*4;
            float4 v = *(const float4*)&d_go[(size_t)(m0+m)*256 + kc*32 + k4];
            As[k4+0][m]=v.x; As[k4+1][m]=v.y; As[k4+2][m]=v.z; As[k4+3][m]=v.w;
        }
        for (int i = tid; i < 32*16; i += 256) {
            int k = i >> 4, n4 = (i & 15)*4;
            *(float4*)&Bs[k][n4] = *(const float4*)&d_wxt[(size_t)(kc*32+k)*64 + n4];
        }
        __syncthreads();
#pragma unroll 4
        for (int k = 0; k < 32; k++) {
            float4 a0 = *(const float4*)&As[k][ty*8];
            float4 a1 = *(const float4*)&As[k][ty*8+4];
            ulonglong2 b0 = *(const ulonglong2*)&Bs[k][tx*8];
            ulonglong2 b1 = *(const ulonglong2*)&Bs[k][tx*8+4];
            ROW8(acc[0], a0.x) ROW8(acc[1], a0.y) ROW8(acc[2], a0.z) ROW8(acc[3], a0.w)
            ROW8(acc[4], a1.x) ROW8(acc[5], a1.y) ROW8(acc[6], a1.z) ROW8(acc[7], a1.w)
        }
    }
#pragma unroll
    for (int i=0;i<8;i++) {
        int m = m0 + ty*8 + i;
        float o[8];
#pragma unroll
        for (int j=0;j<4;j++) UPK2(o[2*j], o[2*j+1], acc[i][j]);
        *(float4*)&d_wx[(size_t)m*64 + tx*8]     = make_float4(o[0],o[1],o[2],o[3]);
        *(float4*)&d_wx[(size_t)m*64 + tx*8 + 4] = make_float4(o[4],o[5],o[6],o[7]);
    }
}

// ---------------- gx[b,c] = sum_s go[b,s,c] * xhat[b,s] -----------------------
__global__ __launch_bounds__(256) void k_gx(const float* __restrict__ x_raw) {
    int b = blockIdx.x;
    int c = threadIdx.x;
    __shared__ float xh[64];
    if (c < 64) xh[c] = 2.f*x_raw[b*64+c] - 3.f;
    __syncthreads();
    float acc = 0.f;
    const float* g = d_go + (size_t)b*64*256;
#pragma unroll 8
    for (int s=0;s<64;s++) acc += g[s*256+c]*xh[s];
    d_gx[(size_t)b*256 + c] = acc;
}

// ---------------- final per-batch: z0, GD loop, output ------------------------
__global__ __launch_bounds__(256) void k_final(const float* __restrict__ Wz,
                                               float* __restrict__ outp) {
    int b = blockIdx.x, tid = threadIdx.x;
    __shared__ float Ws[64][65];
    __shared__ float As[64][65];
    __shared__ float hy[64], zv[64], wh[64], t1[64], t2[64];
    __shared__ float gxs[256];
    for (int i=tid;i<4096;i+=256) Ws[i>>6][i&63] = d_wx[(size_t)b*4096 + i];
    for (int i=tid;i<4096;i+=256) As[i>>6][i&63] = d_HtH[(size_t)b*4096 + i];
    if (tid<64) hy[tid] = d_Hty[b*64+tid];
    gxs[tid] = d_gx[(size_t)b*256 + tid];
    __syncthreads();
    if (tid<64) {
        float a=0.f;
        const float* wz = Wz + tid*256;
#pragma unroll 8
        for (int c=0;c<256;c++) a += wz[c]*gxs[c];
        zv[tid] = a;
        float w=0.f;
#pragma unroll
        for (int s=0;s<64;s++) w += Ws[s][tid]*hy[s];
        wh[tid] = w;
    }
    __syncthreads();
    for (int it=0; it<10; it++) {
        if (tid<64) { float a=0.f;
#pragma unroll
            for (int zc=0;zc<64;zc++) a += Ws[tid][zc]*zv[zc];
            t1[tid]=a; }
        __syncthreads();
        if (tid<64) { float a=0.f;
#pragma unroll
            for (int u=0;u<64;u++) a += As[tid][u]*t1[u];
            t2[tid]=a; }
        __syncthreads();
        if (tid<64) { float a=0.f;
#pragma unroll
            for (int s=0;s<64;s++) a += Ws[s][tid]*t2[s];
            zv[tid] += 2e-6f*(wh[tid]-a); }
        __syncthreads();
    }
    if (tid<64) {
        float a=0.f;
#pragma unroll
        for (int zc=0;zc<64;zc++) a += Ws[tid][zc]*zv[zc];
        outp[b*64+tid] = a;
    }
}

// ---------------- launch -------------------------------------------------------
extern "C" void kernel_launch(void* const* d_in, const int* in_sizes, int n_in,
                              void* d_out, int out_size) {
    const float* y     = (const float*)d_in[0];
    const float* H     = (const float*)d_in[1];
    const float* xraw  = (const float*)d_in[2];
    const float* wih   = (const float*)d_in[3];
    const float* whh   = (const float*)d_in[4];
    const float* bih   = (const float*)d_in[5];
    const float* bhh   = (const float*)d_in[6];
    const float* Wz    = (const float*)d_in[7];
    const float* Wx    = (const float*)d_in[8];
    const float* gamma = (const float*)d_in[9];
    const float* beta  = (const float*)d_in[10];
    float* outp = (float*)d_out;

    cudaFuncSetAttribute(k_xg, cudaFuncAttributeMaxDynamicSharedMemorySize, XG_SMEM);

    k_init<<<8192,256>>>();                                   // slot 0
    k_prep<<<384,256>>>(wih, whh, Wx);                        // slot 1
    k_hth<<<BATCH,256>>>(H, y);                               // slot 2
    k_bn<<<1,768>>>(gamma, beta, wih);                        // slot 3
    k_xg<<<dim3(3,64,128),256,XG_SMEM>>>(bih);                // slot 4
    for (int step=0; step<64; step++) {                       // slot 5 = gru step 0 (profiled)
        k_gru_step<<<dim3(256,2),256>>>(bhh, step, step & 1);
    }
    k_wx<<<2048,256>>>();
    k_gx<<<BATCH,256>>>(xraw);
    k_final<<<BATCH,256>>>(Wz, outp);
}

// round 14
// speedup vs baseline: 1.2702x; 1.0749x over previous
#include <cuda_runtime.h>
#include <math.h>

#define BATCH 8192
#define SEQ 64
#define FEAT 65
#define KXG 68
#define HID 128
#define G3 384
#define DZ 64

typedef unsigned long long u64;

// ---------------- packed fp32x2 FMA (FFMA2) ---------------------------------
#define PK2(d, x)       asm("mov.b64 %0, {%1, %1};" : "=l"(d) : "f"(x))
#define FMA2(c, a, b)   asm("fma.rn.f32x2 %0, %1, %2, %0;" : "+l"(c) : "l"(a), "l"(b))
#define UPK2(lo, hi, s) asm("mov.b64 {%0, %1}, %2;" : "=f"(lo), "=f"(hi) : "l"(s))

#define ROW8(acc_i, av)  { u64 aa_; PK2(aa_, av); \
    FMA2(acc_i[0], aa_, b0.x); FMA2(acc_i[1], aa_, b0.y); \
    FMA2(acc_i[2], aa_, b1.x); FMA2(acc_i[3], aa_, b1.y); }

// ---------------- cp.async helpers ------------------------------------------
__device__ __forceinline__ unsigned su32(const void* p) {
    return (unsigned)__cvta_generic_to_shared(p);
}
#define CPA16(dst, src) asm volatile("cp.async.cg.shared.global [%0], [%1], 16;" :: "r"(dst), "l"(src))
#define CPC()           asm volatile("cp.async.commit_group;" ::: "memory")
#define CPW(N)          asm volatile("cp.async.wait_group %0;" :: "n"(N) : "memory")

// ---------------- scratch (device globals; no allocation allowed) ----------
__device__ float  d_HtH[BATCH*64*64];
__device__ float  d_Hty[BATCH*64];
__device__ double d_stats[128];
__device__ float  d_scale[64];
__device__ float  d_shift[64];
__device__ float  d_wsum[2*G3];
__device__ float  d_xg[402653184];               // (2*SEQ*BATCH*G3)
__device__ float  d_h[2][2*BATCH*HID];
__device__ float  d_go[134217728];               // (BATCH*SEQ*256)
__device__ float  d_wx[BATCH*SEQ*DZ];
__device__ float  d_gx[BATCH*256];
__device__ float  d_wih_t[2*KXG*G3];
__device__ float  d_whh_t[2*HID*G3];
__device__ float  d_wxt[256*DZ];

// ---------------- init -------------------------------------------------------
__global__ __launch_bounds__(256) void k_init() {
    int idx = blockIdx.x*256 + threadIdx.x;
    if (idx < 2*BATCH*HID) d_h[0][idx] = 0.f;
    if (blockIdx.x == 0 && threadIdx.x < 128) d_stats[threadIdx.x] = 0.0;
}

// ---------------- weight prep: transpose to k-major --------------------------
__global__ __launch_bounds__(256) void k_prep(const float* __restrict__ wih,
                                              const float* __restrict__ whh,
                                              const float* __restrict__ wx) {
    int idx = blockIdx.x*256 + threadIdx.x;
    if (idx < 2*KXG*G3) {
        int g = idx % G3; int rest = idx / G3;
        int f = rest % KXG; int dir = rest / KXG;
        d_wih_t[idx] = (f < FEAT) ? wih[((size_t)dir*G3 + g)*FEAT + f] : 0.f;
    }
    if (idx < 2*HID*G3) {
        int g = idx % G3; int rest = idx / G3;
        int k = rest % HID; int dir = rest / HID;
        d_whh_t[idx] = whh[((size_t)dir*G3 + g)*HID + k];
    }
    if (idx < 256*DZ) {
        int n = idx & 63, k = idx >> 6;
        d_wxt[idx] = wx[n*256 + k];
    }
}

// ---------------- per-batch HtH, Hty + BN partial stats (f32x2) --------------
__global__ __launch_bounds__(256) void k_hth(const float* __restrict__ Hg,
                                             const float* __restrict__ yg) {
    int b = blockIdx.x;
    __shared__ __align__(16) float Hs[64][68];
    __shared__ float ys[64], hty[64], csum[64], csq[64];
    int tid = threadIdx.x;
    const float* Hb = Hg + (size_t)b*4096;
    for (int i = tid; i < 4096; i += 256) Hs[i>>6][i&63] = Hb[i];
    if (tid < 64) { ys[tid] = yg[b*64+tid]; csum[tid]=0.f; csq[tid]=0.f; }
    __syncthreads();
    if (tid < 64) {
        float a = 0.f;
#pragma unroll
        for (int r=0;r<64;r++) a += Hs[r][tid]*ys[r];
        hty[tid] = a;
        d_Hty[b*64+tid] = a;
    }
    int ty = tid >> 4, tx = tid & 15;
    u64 acc[4][2] = {};
#pragma unroll 8
    for (int r = 0; r < 64; r++) {
        float4 a = *(const float4*)&Hs[r][ty*4];
        ulonglong2 bb = *(const ulonglong2*)&Hs[r][tx*4];
        u64 aa;
        PK2(aa, a.x); FMA2(acc[0][0], aa, bb.x); FMA2(acc[0][1], aa, bb.y);
        PK2(aa, a.y); FMA2(acc[1][0], aa, bb.x); FMA2(acc[1][1], aa, bb.y);
        PK2(aa, a.z); FMA2(acc[2][0], aa, bb.x); FMA2(acc[2][1], aa, bb.y);
        PK2(aa, a.w); FMA2(acc[3][0], aa, bb.x); FMA2(acc[3][1], aa, bb.y);
    }
    float* outp = d_HtH + (size_t)b*4096;
#pragma unroll
    for (int i=0;i<4;i++) {
        float4 v;
        UPK2(v.x, v.y, acc[i][0]);
        UPK2(v.z, v.w, acc[i][1]);
        *reinterpret_cast<float4*>(&outp[(ty*4+i)*64 + tx*4]) = v;
        float s1 = v.x+v.y+v.z+v.w;
        float s2 = v.x*v.x+v.y*v.y+v.z*v.z+v.w*v.w;
        atomicAdd(&csum[ty*4+i], s1);
        atomicAdd(&csq[ty*4+i],  s2);
    }
    __syncthreads();
    if (tid < 64) {
        float v = hty[tid];
        atomicAdd(&d_stats[tid],    (double)(csum[tid]+v));
        atomicAdd(&d_stats[64+tid], (double)(csq[tid]+v*v));
    }
}

// ---------------- finalize BN scale/shift + W_ih row sums --------------------
__global__ void k_bn(const float* __restrict__ gamma, const float* __restrict__ beta,
                     const float* __restrict__ wih) {
    int tid = threadIdx.x;
    if (tid < 64) {
        double n  = (double)BATCH*FEAT;
        double mu = d_stats[tid]/n;
        double var = d_stats[64+tid]/n - mu*mu;
        double sc = (double)gamma[tid] / sqrt(var + 1e-5);
        d_scale[tid] = (float)sc;
        d_shift[tid] = beta[tid] - (float)(mu*sc);
    }
    if (tid < 2*G3) {
        float s = 0.f;
        const float* w = wih + tid*FEAT;
        for (int f=0; f<FEAT; f++) s += w[f];
        d_wsum[tid] = s;
    }
}

// ---------------- GRU input gates: 128x128 tile, f32x2 ------------------------
#define XG_SMEM (2*KXG*132*4)
__global__ __launch_bounds__(256,2) void k_xg(const float* __restrict__ bih) {
    extern __shared__ __align__(16) float xs[];
    float (*As)[132] = (float(*)[132])xs;
    float (*Bs)[132] = (float(*)[132])(xs + KXG*132);
    int n0 = blockIdx.x*128, b0 = blockIdx.y*128;
    int z = blockIdx.z, dir = z >> 6, s = z & 63;
    int tid = threadIdx.x;
    for (int i = tid; i < 128*16; i += 256) {
        int m = i >> 4, f4 = (i & 15)*4;
        float4 v = *(const float4*)&d_HtH[(size_t)(b0+m)*4096 + s*64 + f4];
        As[f4+0][m]=v.x; As[f4+1][m]=v.y; As[f4+2][m]=v.z; As[f4+3][m]=v.w;
    }
    if (tid < 128) {
        As[64][tid] = d_Hty[(b0+tid)*64 + s];
        As[65][tid] = 0.f; As[66][tid] = 0.f; As[67][tid] = 0.f;
    }
    for (int i = tid; i < KXG*32; i += 256) {
        int f = i >> 5, n4 = (i & 31)*4;
        *(float4*)&Bs[f][n4] =
            *(const float4*)&d_wih_t[((size_t)dir*KXG + f)*G3 + n0 + n4];
    }
    __syncthreads();
    int ty = tid >> 4, tx = tid & 15;
    u64 acc[8][4] = {};
#pragma unroll 4
    for (int k = 0; k < KXG; k++) {
        float4 a0 = *(const float4*)&As[k][ty*8];
        float4 a1 = *(const float4*)&As[k][ty*8+4];
        ulonglong2 b0 = *(const ulonglong2*)&Bs[k][tx*8];
        ulonglong2 b1 = *(const ulonglong2*)&Bs[k][tx*8+4];
        ROW8(acc[0], a0.x) ROW8(acc[1], a0.y) ROW8(acc[2], a0.z) ROW8(acc[3], a0.w)
        ROW8(acc[4], a1.x) ROW8(acc[5], a1.y) ROW8(acc[6], a1.z) ROW8(acc[7], a1.w)
    }
    float sc = d_scale[s], sh = d_shift[s];
    int gn = n0 + tx*8;
    float wv[8];
#pragma unroll
    for (int j=0;j<8;j++) wv[j] = sh*d_wsum[dir*G3+gn+j] + bih[dir*G3+gn+j];
    size_t zb = ((size_t)z*BATCH + b0)*G3;
#pragma unroll
    for (int i=0;i<8;i++) {
        int m = ty*8 + i;
        float o[8];
#pragma unroll
        for (int j=0;j<4;j++) {
            float lo, hi; UPK2(lo, hi, acc[i][j]);
            o[2*j]   = lo*sc + wv[2*j];
            o[2*j+1] = hi*sc + wv[2*j+1];
        }
        *(float4*)&d_xg[zb + (size_t)m*G3 + gn]     = make_float4(o[0],o[1],o[2],o[3]);
        *(float4*)&d_xg[zb + (size_t)m*G3 + gn + 4] = make_float4(o[4],o[5],o[6],o[7]);
    }
}

// ---------------- FUSED GRU step: cp.async double-buffered B ------------------
#define GRU_B_BYTES (32*388*4)                       // 49664
#define GRU_SMEM    (2*GRU_B_BYTES + 32*36*4)        // 103936
__global__ __launch_bounds__(256,2) void k_gru_step(const float* __restrict__ bhh,
                                                    int step, int ping) {
    extern __shared__ __align__(16) char gsm[];
    float (*BsA)[388] = (float(*)[388])gsm;
    float (*BsB)[388] = (float(*)[388])(gsm + GRU_B_BYTES);
    float (*As)[36]   = (float(*)[36])(gsm + 2*GRU_B_BYTES);
    int dir = blockIdx.y, b0 = blockIdx.x*32;
    int sx = dir ? (63 - step) : step;
    int tid = threadIdx.x, ty = tid >> 6, tx = tid & 63;
    const float* hp = d_h[ping] + (size_t)dir*BATCH*HID;
    const float* wt = d_whh_t + (size_t)dir*HID*G3;
    u64 acc[8][3] = {};
    int fm = tid >> 3, fk4 = (tid & 7)*4;
    // prologue: prefetch B chunk 0 into BsA
#pragma unroll
    for (int p = 0; p < 12; p++) {
        int i = p*256 + tid;
        int k = i / 96, n4 = (i - k*96)*4;
        CPA16(su32(&BsA[k][n4]), wt + (size_t)k*G3 + n4);
    }
    CPC();
    for (int kc = 0; kc < 4; kc++) {
        __syncthreads();                       // prior compute done (As + both B bufs safe)
        float4 av = *(const float4*)&hp[(size_t)(b0+fm)*HID + kc*32 + fk4];
        if (kc < 3) {
            float (*Bn)[388] = ((kc+1) & 1) ? BsB : BsA;
#pragma unroll
            for (int p = 0; p < 12; p++) {
                int i = p*256 + tid;
                int k = i / 96, n4 = (i - k*96)*4;
                CPA16(su32(&Bn[k][n4]), wt + (size_t)((kc+1)*32+k)*G3 + n4);
            }
            CPC();
            CPW(1);                            // chunk kc ready; kc+1 in flight
        } else {
            CPW(0);
        }
        As[fk4+0][fm]=av.x; As[fk4+1][fm]=av.y; As[fk4+2][fm]=av.z; As[fk4+3][fm]=av.w;
        __syncthreads();                       // As + Bs[kc] visible to all
        float (*Bc)[388] = (kc & 1) ? BsB : BsA;
#pragma unroll 4
        for (int k = 0; k < 32; k++) {
            float4 a0 = *(const float4*)&As[k][ty*8];
            float4 a1 = *(const float4*)&As[k][ty*8+4];
            u64 br = *(const u64*)&Bc[k][tx*2];
            u64 bz = *(const u64*)&Bc[k][128 + tx*2];
            u64 bn = *(const u64*)&Bc[k][256 + tx*2];
            u64 aa;
            PK2(aa, a0.x); FMA2(acc[0][0], aa, br); FMA2(acc[0][1], aa, bz); FMA2(acc[0][2], aa, bn);
            PK2(aa, a0.y); FMA2(acc[1][0], aa, br); FMA2(acc[1][1], aa, bz); FMA2(acc[1][2], aa, bn);
            PK2(aa, a0.z); FMA2(acc[2][0], aa, br); FMA2(acc[2][1], aa, bz); FMA2(acc[2][2], aa, bn);
            PK2(aa, a0.w); FMA2(acc[3][0], aa, br); FMA2(acc[3][1], aa, bz); FMA2(acc[3][2], aa, bn);
            PK2(aa, a1.x); FMA2(acc[4][0], aa, br); FMA2(acc[4][1], aa, bz); FMA2(acc[4][2], aa, bn);
            PK2(aa, a1.y); FMA2(acc[5][0], aa, br); FMA2(acc[5][1], aa, bz); FMA2(acc[5][2], aa, bn);
            PK2(aa, a1.z); FMA2(acc[6][0], aa, br); FMA2(acc[6][1], aa, bz); FMA2(acc[6][2], aa, bn);
            PK2(aa, a1.w); FMA2(acc[7][0], aa, br); FMA2(acc[7][1], aa, bz); FMA2(acc[7][2], aa, bn);
        }
    }
    int j0 = tx*2;
    const float* bh = bhh + dir*G3;
    float2 bhr = *(const float2*)&bh[j0];
    float2 bhz = *(const float2*)&bh[128 + j0];
    float2 bhn = *(const float2*)&bh[256 + j0];
    size_t xzb = ((size_t)(dir*64 + sx)*BATCH + b0)*G3;
    float* hout = d_h[1-ping] + (size_t)dir*BATCH*HID;
#pragma unroll
    for (int i = 0; i < 8; i++) {
        int m = ty*8 + i, b = b0 + m;
        const float* xgp = &d_xg[xzb + (size_t)m*G3];
        float2 xr = *(const float2*)&xgp[j0];
        float2 xz = *(const float2*)&xgp[128 + j0];
        float2 xn = *(const float2*)&xgp[256 + j0];
        float2 hpv = *(const float2*)&hp[(size_t)b*HID + j0];
        float hr0,hr1,hz0,hz1,hn0,hn1;
        UPK2(hr0,hr1,acc[i][0]); UPK2(hz0,hz1,acc[i][1]); UPK2(hn0,hn1,acc[i][2]);
        float r0 = 1.f/(1.f + expf(-(xr.x + hr0 + bhr.x)));
        float r1 = 1.f/(1.f + expf(-(xr.y + hr1 + bhr.y)));
        float z0 = 1.f/(1.f + expf(-(xz.x + hz0 + bhz.x)));
        float z1 = 1.f/(1.f + expf(-(xz.y + hz1 + bhz.y)));
        float n0 = tanhf(xn.x + r0*(hn0 + bhn.x));
        float n1 = tanhf(xn.y + r1*(hn1 + bhn.y));
        float h0 = (1.f - z0)*n0 + z0*hpv.x;
        float h1 = (1.f - z1)*n1 + z1*hpv.y;
        *(float2*)&hout[(size_t)b*HID + j0] = make_float2(h0, h1);
        *(float2*)&d_go[((size_t)b*64 + sx)*256 + dir*128 + j0] = make_float2(h0, h1);
    }
}

// ---------------- w_x = go @ Wx^T: 256x64 tile, f32x2 -------------------------
__global__ __launch_bounds__(256,2) void k_wx() {
    __shared__ __align__(16) float As[32][260];
    __shared__ __align__(16) float Bs[32][68];
    int m0 = blockIdx.x*256;
    int tid = threadIdx.x, ty = tid >> 3, tx = tid & 7;
    u64 acc[8][4] = {};
    for (int kc = 0; kc < 8; kc++) {
        __syncthreads();
#pragma unroll
        for (int p = 0; p < 8; p++) {
            int i = p*256 + tid;
            int m = i >> 3, k4 = (i & 7)*4;
            float4 v = *(const float4*)&d_go[(size_t)(m0+m)*256 + kc*32 + k4];
            As[k4+0][m]=v.x; As[k4+1][m]=v.y; As[k4+2][m]=v.z; As[k4+3][m]=v.w;
        }
        for (int i = tid; i < 32*16; i += 256) {
            int k = i >> 4, n4 = (i & 15)*4;
            *(float4*)&Bs[k][n4] = *(const float4*)&d_wxt[(size_t)(kc*32+k)*64 + n4];
        }
        __syncthreads();
#pragma unroll 4
        for (int k = 0; k < 32; k++) {
            float4 a0 = *(const float4*)&As[k][ty*8];
            float4 a1 = *(const float4*)&As[k][ty*8+4];
            ulonglong2 b0 = *(const ulonglong2*)&Bs[k][tx*8];
            ulonglong2 b1 = *(const ulonglong2*)&Bs[k][tx*8+4];
            ROW8(acc[0], a0.x) ROW8(acc[1], a0.y) ROW8(acc[2], a0.z) ROW8(acc[3], a0.w)
            ROW8(acc[4], a1.x) ROW8(acc[5], a1.y) ROW8(acc[6], a1.z) ROW8(acc[7], a1.w)
        }
    }
#pragma unroll
    for (int i=0;i<8;i++) {
        int m = m0 + ty*8 + i;
        float o[8];
#pragma unroll
        for (int j=0;j<4;j++) UPK2(o[2*j], o[2*j+1], acc[i][j]);
        *(float4*)&d_wx[(size_t)m*64 + tx*8]     = make_float4(o[0],o[1],o[2],o[3]);
        *(float4*)&d_wx[(size_t)m*64 + tx*8 + 4] = make_float4(o[4],o[5],o[6],o[7]);
    }
}

// ---------------- gx[b,c] = sum_s go[b,s,c] * xhat[b,s] -----------------------
__global__ __launch_bounds__(256) void k_gx(const float* __restrict__ x_raw) {
    int b = blockIdx.x;
    int c = threadIdx.x;
    __shared__ float xh[64];
    if (c < 64) xh[c] = 2.f*x_raw[b*64+c] - 3.f;
    __syncthreads();
    float acc = 0.f;
    const float* g = d_go + (size_t)b*64*256;
#pragma unroll 8
    for (int s=0;s<64;s++) acc += g[s*256+c]*xh[s];
    d_gx[(size_t)b*256 + c] = acc;
}

// ---------------- final per-batch: z0, GD loop, output ------------------------
__global__ __launch_bounds__(256) void k_final(const float* __restrict__ Wz,
                                               float* __restrict__ outp) {
    int b = blockIdx.x, tid = threadIdx.x;
    __shared__ float Ws[64][65];
    __shared__ float As[64][65];
    __shared__ float hy[64], zv[64], wh[64], t1[64], t2[64];
    __shared__ float gxs[256];
    for (int i=tid;i<4096;i+=256) Ws[i>>6][i&63] = d_wx[(size_t)b*4096 + i];
    for (int i=tid;i<4096;i+=256) As[i>>6][i&63] = d_HtH[(size_t)b*4096 + i];
    if (tid<64) hy[tid] = d_Hty[b*64+tid];
    gxs[tid] = d_gx[(size_t)b*256 + tid];
    __syncthreads();
    if (tid<64) {
        float a=0.f;
        const float* wz = Wz + tid*256;
#pragma unroll 8
        for (int c=0;c<256;c++) a += wz[c]*gxs[c];
        zv[tid] = a;
        float w=0.f;
#pragma unroll
        for (int s=0;s<64;s++) w += Ws[s][tid]*hy[s];
        wh[tid] = w;
    }
    __syncthreads();
    for (int it=0; it<10; it++) {
        if (tid<64) { float a=0.f;
#pragma unroll
            for (int zc=0;zc<64;zc++) a += Ws[tid][zc]*zv[zc];
            t1[tid]=a; }
        __syncthreads();
        if (tid<64) { float a=0.f;
#pragma unroll
            for (int u=0;u<64;u++) a += As[tid][u]*t1[u];
            t2[tid]=a; }
        __syncthreads();
        if (tid<64) { float a=0.f;
#pragma unroll
            for (int s=0;s<64;s++) a += Ws[s][tid]*t2[s];
            zv[tid] += 2e-6f*(wh[tid]-a); }
        __syncthreads();
    }
    if (tid<64) {
        float a=0.f;
#pragma unroll
        for (int zc=0;zc<64;zc++) a += Ws[tid][zc]*zv[zc];
        outp[b*64+tid] = a;
    }
}

// ---------------- launch -------------------------------------------------------
extern "C" void kernel_launch(void* const* d_in, const int* in_sizes, int n_in,
                              void* d_out, int out_size) {
    const float* y     = (const float*)d_in[0];
    const float* H     = (const float*)d_in[1];
    const float* xraw  = (const float*)d_in[2];
    const float* wih   = (const float*)d_in[3];
    const float* whh   = (const float*)d_in[4];
    const float* bih   = (const float*)d_in[5];
    const float* bhh   = (const float*)d_in[6];
    const float* Wz    = (const float*)d_in[7];
    const float* Wx    = (const float*)d_in[8];
    const float* gamma = (const float*)d_in[9];
    const float* beta  = (const float*)d_in[10];
    float* outp = (float*)d_out;

    cudaFuncSetAttribute(k_xg, cudaFuncAttributeMaxDynamicSharedMemorySize, XG_SMEM);
    cudaFuncSetAttribute(k_gru_step, cudaFuncAttributeMaxDynamicSharedMemorySize, GRU_SMEM);

    k_init<<<8192,256>>>();                                   // slot 0
    k_prep<<<384,256>>>(wih, whh, Wx);                        // slot 1
    k_hth<<<BATCH,256>>>(H, y);                               // slot 2
    k_bn<<<1,768>>>(gamma, beta, wih);                        // slot 3
    k_xg<<<dim3(3,64,128),256,XG_SMEM>>>(bih);                // slot 4
    for (int step=0; step<64; step++) {                       // slot 5 = gru step 0 (profiled)
        k_gru_step<<<dim3(256,2),256,GRU_SMEM>>>(bhh, step, step & 1);
    }
    k_wx<<<2048,256>>>();
    k_gx<<<BATCH,256>>>(xraw);
    k_final<<<BATCH,256>>>(Wz, outp);
}

// round 15
// speedup vs baseline: 1.3236x; 1.0421x over previous
#include <cuda_runtime.h>
#include <math.h>

#define BATCH 8192
#define SEQ 64
#define FEAT 65
#define KXG 68
#define HID 128
#define G3 384
#define DZ 64

typedef unsigned long long u64;

// ---------------- packed fp32x2 FMA (FFMA2) ---------------------------------
#define PK2(d, x)       asm("mov.b64 %0, {%1, %1};" : "=l"(d) : "f"(x))
#define FMA2(c, a, b)   asm("fma.rn.f32x2 %0, %1, %2, %0;" : "+l"(c) : "l"(a), "l"(b))
#define UPK2(lo, hi, s) asm("mov.b64 {%0, %1}, %2;" : "=f"(lo), "=f"(hi) : "l"(s))

#define ROW8(acc_i, av)  { u64 aa_; PK2(aa_, av); \
    FMA2(acc_i[0], aa_, b0.x); FMA2(acc_i[1], aa_, b0.y); \
    FMA2(acc_i[2], aa_, b1.x); FMA2(acc_i[3], aa_, b1.y); }

// ---------------- cp.async helpers ------------------------------------------
__device__ __forceinline__ unsigned su32(const void* p) {
    return (unsigned)__cvta_generic_to_shared(p);
}
#define CPA16(dst, src) asm volatile("cp.async.cg.shared.global [%0], [%1], 16;" :: "r"(dst), "l"(src))
#define CPC()           asm volatile("cp.async.commit_group;" ::: "memory")
#define CPW(N)          asm volatile("cp.async.wait_group %0;" :: "n"(N) : "memory")

// ---------------- scratch (device globals; no allocation allowed) ----------
__device__ float  d_HtH[BATCH*64*64];
__device__ float  d_Hty[BATCH*64];
__device__ double d_stats[128];
__device__ float  d_scale[64];
__device__ float  d_shift[64];
__device__ float  d_wsum[2*G3];
__device__ float  d_xg[402653184];               // (2*SEQ*BATCH*G3)
__device__ float  d_go[134217728];               // (BATCH*SEQ*256)
__device__ float  d_wx[BATCH*SEQ*DZ];
__device__ float  d_gx[BATCH*256];
__device__ float  d_wih_t[2*KXG*G3];
__device__ float  d_whh_t[2*HID*G3];
__device__ float  d_wxt[256*DZ];

// ---------------- init -------------------------------------------------------
__global__ __launch_bounds__(256) void k_init() {
    if (blockIdx.x == 0 && threadIdx.x < 128) d_stats[threadIdx.x] = 0.0;
}

// ---------------- weight prep: transpose to k-major --------------------------
__global__ __launch_bounds__(256) void k_prep(const float* __restrict__ wih,
                                              const float* __restrict__ whh,
                                              const float* __restrict__ wx) {
    int idx = blockIdx.x*256 + threadIdx.x;
    if (idx < 2*KXG*G3) {
        int g = idx % G3; int rest = idx / G3;
        int f = rest % KXG; int dir = rest / KXG;
        d_wih_t[idx] = (f < FEAT) ? wih[((size_t)dir*G3 + g)*FEAT + f] : 0.f;
    }
    if (idx < 2*HID*G3) {
        int g = idx % G3; int rest = idx / G3;
        int k = rest % HID; int dir = rest / HID;
        d_whh_t[idx] = whh[((size_t)dir*G3 + g)*HID + k];
    }
    if (idx < 256*DZ) {
        int n = idx & 63, k = idx >> 6;
        d_wxt[idx] = wx[n*256 + k];
    }
}

// ---------------- per-batch HtH, Hty + BN partial stats (f32x2) --------------
__global__ __launch_bounds__(256) void k_hth(const float* __restrict__ Hg,
                                             const float* __restrict__ yg) {
    int b = blockIdx.x;
    __shared__ __align__(16) float Hs[64][68];
    __shared__ float ys[64], hty[64], csum[64], csq[64];
    int tid = threadIdx.x;
    const float* Hb = Hg + (size_t)b*4096;
    for (int i = tid; i < 4096; i += 256) Hs[i>>6][i&63] = Hb[i];
    if (tid < 64) { ys[tid] = yg[b*64+tid]; csum[tid]=0.f; csq[tid]=0.f; }
    __syncthreads();
    if (tid < 64) {
        float a = 0.f;
#pragma unroll
        for (int r=0;r<64;r++) a += Hs[r][tid]*ys[r];
        hty[tid] = a;
        d_Hty[b*64+tid] = a;
    }
    int ty = tid >> 4, tx = tid & 15;
    u64 acc[4][2] = {};
#pragma unroll 8
    for (int r = 0; r < 64; r++) {
        float4 a = *(const float4*)&Hs[r][ty*4];
        ulonglong2 bb = *(const ulonglong2*)&Hs[r][tx*4];
        u64 aa;
        PK2(aa, a.x); FMA2(acc[0][0], aa, bb.x); FMA2(acc[0][1], aa, bb.y);
        PK2(aa, a.y); FMA2(acc[1][0], aa, bb.x); FMA2(acc[1][1], aa, bb.y);
        PK2(aa, a.z); FMA2(acc[2][0], aa, bb.x); FMA2(acc[2][1], aa, bb.y);
        PK2(aa, a.w); FMA2(acc[3][0], aa, bb.x); FMA2(acc[3][1], aa, bb.y);
    }
    float* outp = d_HtH + (size_t)b*4096;
#pragma unroll
    for (int i=0;i<4;i++) {
        float4 v;
        UPK2(v.x, v.y, acc[i][0]);
        UPK2(v.z, v.w, acc[i][1]);
        *reinterpret_cast<float4*>(&outp[(ty*4+i)*64 + tx*4]) = v;
        float s1 = v.x+v.y+v.z+v.w;
        float s2 = v.x*v.x+v.y*v.y+v.z*v.z+v.w*v.w;
        atomicAdd(&csum[ty*4+i], s1);
        atomicAdd(&csq[ty*4+i],  s2);
    }
    __syncthreads();
    if (tid < 64) {
        float v = hty[tid];
        atomicAdd(&d_stats[tid],    (double)(csum[tid]+v));
        atomicAdd(&d_stats[64+tid], (double)(csq[tid]+v*v));
    }
}

// ---------------- finalize BN scale/shift + W_ih row sums --------------------
__global__ void k_bn(const float* __restrict__ gamma, const float* __restrict__ beta,
                     const float* __restrict__ wih) {
    int tid = threadIdx.x;
    if (tid < 64) {
        double n  = (double)BATCH*FEAT;
        double mu = d_stats[tid]/n;
        double var = d_stats[64+tid]/n - mu*mu;
        double sc = (double)gamma[tid] / sqrt(var + 1e-5);
        d_scale[tid] = (float)sc;
        d_shift[tid] = beta[tid] - (float)(mu*sc);
    }
    if (tid < 2*G3) {
        float s = 0.f;
        const float* w = wih + tid*FEAT;
        for (int f=0; f<FEAT; f++) s += w[f];
        d_wsum[tid] = s;
    }
}

// ---------------- GRU input gates: 128x128 tile, f32x2 ------------------------
#define XG_SMEM (2*KXG*132*4)
__global__ __launch_bounds__(256,2) void k_xg(const float* __restrict__ bih) {
    extern __shared__ __align__(16) float xs[];
    float (*As)[132] = (float(*)[132])xs;
    float (*Bs)[132] = (float(*)[132])(xs + KXG*132);
    int n0 = blockIdx.x*128, b0 = blockIdx.y*128;
    int z = blockIdx.z, dir = z >> 6, s = z & 63;
    int tid = threadIdx.x;
    for (int i = tid; i < 128*16; i += 256) {
        int m = i >> 4, f4 = (i & 15)*4;
        float4 v = *(const float4*)&d_HtH[(size_t)(b0+m)*4096 + s*64 + f4];
        As[f4+0][m]=v.x; As[f4+1][m]=v.y; As[f4+2][m]=v.z; As[f4+3][m]=v.w;
    }
    if (tid < 128) {
        As[64][tid] = d_Hty[(b0+tid)*64 + s];
        As[65][tid] = 0.f; As[66][tid] = 0.f; As[67][tid] = 0.f;
    }
    for (int i = tid; i < KXG*32; i += 256) {
        int f = i >> 5, n4 = (i & 31)*4;
        *(float4*)&Bs[f][n4] =
            *(const float4*)&d_wih_t[((size_t)dir*KXG + f)*G3 + n0 + n4];
    }
    __syncthreads();
    int ty = tid >> 4, tx = tid & 15;
    u64 acc[8][4] = {};
#pragma unroll 4
    for (int k = 0; k < KXG; k++) {
        float4 a0 = *(const float4*)&As[k][ty*8];
        float4 a1 = *(const float4*)&As[k][ty*8+4];
        ulonglong2 b0 = *(const ulonglong2*)&Bs[k][tx*8];
        ulonglong2 b1 = *(const ulonglong2*)&Bs[k][tx*8+4];
        ROW8(acc[0], a0.x) ROW8(acc[1], a0.y) ROW8(acc[2], a0.z) ROW8(acc[3], a0.w)
        ROW8(acc[4], a1.x) ROW8(acc[5], a1.y) ROW8(acc[6], a1.z) ROW8(acc[7], a1.w)
    }
    float sc = d_scale[s], sh = d_shift[s];
    int gn = n0 + tx*8;
    float wv[8];
#pragma unroll
    for (int j=0;j<8;j++) wv[j] = sh*d_wsum[dir*G3+gn+j] + bih[dir*G3+gn+j];
    size_t zb = ((size_t)z*BATCH + b0)*G3;
#pragma unroll
    for (int i=0;i<8;i++) {
        int m = ty*8 + i;
        float o[8];
#pragma unroll
        for (int j=0;j<4;j++) {
            float lo, hi; UPK2(lo, hi, acc[i][j]);
            o[2*j]   = lo*sc + wv[2*j];
            o[2*j+1] = hi*sc + wv[2*j+1];
        }
        *(float4*)&d_xg[zb + (size_t)m*G3 + gn]     = make_float4(o[0],o[1],o[2],o[3]);
        *(float4*)&d_xg[zb + (size_t)m*G3 + gn + 4] = make_float4(o[4],o[5],o[6],o[7]);
    }
}

// ---------------- PERSISTENT GRU: all 64 steps, cp.async B ring, h in smem ----
// grid (256, 2); 256 threads; 2 CTAs/SM (92 KB smem).
// B streamed L2->smem as 16-k chunks, triple-buffered, continuous across steps.
#define CH 16
#define B_CHUNK_BYTES (CH*G3*4)                     // 24576
#define GRUA_SMEM (3*B_CHUNK_BYTES + 128*36*4)      // 73728 + 18432 = 92160
__global__ __launch_bounds__(256,2) void k_gru_all(const float* __restrict__ bhh) {
    extern __shared__ __align__(16) char gsm[];
    float (*Bs)[CH][G3] = (float(*)[CH][G3])gsm;          // [3][16][384]
    float (*Ht)[36]     = (float(*)[36])(gsm + 3*B_CHUNK_BYTES);  // [k=128][m=32]
    int dir = blockIdx.y, b0 = blockIdx.x*32;
    int tid = threadIdx.x, ty = tid >> 6, tx = tid & 63;
    const float* wt = d_whh_t + (size_t)dir*HID*G3;
    // zero h
    for (int i = tid; i < 128*36; i += 256) ((float*)Ht)[i] = 0.f;
    // prologue: prefetch global chunk 0 into slot 0
#pragma unroll
    for (int p = 0; p < 6; p++) {
        int i = p*256 + tid;
        int k = i / 96, n4 = (i - k*96)*4;
        CPA16(su32(&Bs[0][k][n4]), wt + (size_t)k*G3 + n4);
    }
    CPC();

    int j0 = tx*2;
    const float* bh = bhh + dir*G3;
    float2 bhr = *(const float2*)&bh[j0];
    float2 bhz = *(const float2*)&bh[128 + j0];
    float2 bhn = *(const float2*)&bh[256 + j0];
    u64 acc[8][3] = {};
    int slot = 0, nslot = 1;

    for (int kc = 0; kc < 512; kc++) {
        if (kc + 1 < 512) {
            int nc = (kc + 1) & 7;
#pragma unroll
            for (int p = 0; p < 6; p++) {
                int i = p*256 + tid;
                int k = i / 96, n4 = (i - k*96)*4;
                CPA16(su32(&Bs[nslot][k][n4]), wt + (size_t)(nc*CH + k)*G3 + n4);
            }
            CPC();
            CPW(1);
        } else {
            CPW(0);
        }
        __syncthreads();     // chunk kc visible to all; Ht writes from prev epilogue visible
        int c = kc & 7;
#pragma unroll 8
        for (int k = 0; k < CH; k++) {
            int kg = c*CH + k;
            float4 a0 = *(const float4*)&Ht[kg][ty*8];
            float4 a1 = *(const float4*)&Ht[kg][ty*8+4];
            u64 br = *(const u64*)&Bs[slot][k][j0];
            u64 bz = *(const u64*)&Bs[slot][k][128 + j0];
            u64 bn = *(const u64*)&Bs[slot][k][256 + j0];
            u64 aa;
            PK2(aa, a0.x); FMA2(acc[0][0], aa, br); FMA2(acc[0][1], aa, bz); FMA2(acc[0][2], aa, bn);
            PK2(aa, a0.y); FMA2(acc[1][0], aa, br); FMA2(acc[1][1], aa, bz); FMA2(acc[1][2], aa, bn);
            PK2(aa, a0.z); FMA2(acc[2][0], aa, br); FMA2(acc[2][1], aa, bz); FMA2(acc[2][2], aa, bn);
            PK2(aa, a0.w); FMA2(acc[3][0], aa, br); FMA2(acc[3][1], aa, bz); FMA2(acc[3][2], aa, bn);
            PK2(aa, a1.x); FMA2(acc[4][0], aa, br); FMA2(acc[4][1], aa, bz); FMA2(acc[4][2], aa, bn);
            PK2(aa, a1.y); FMA2(acc[5][0], aa, br); FMA2(acc[5][1], aa, bz); FMA2(acc[5][2], aa, bn);
            PK2(aa, a1.z); FMA2(acc[6][0], aa, br); FMA2(acc[6][1], aa, bz); FMA2(acc[6][2], aa, bn);
            PK2(aa, a1.w); FMA2(acc[7][0], aa, br); FMA2(acc[7][1], aa, bz); FMA2(acc[7][2], aa, bn);
        }
        slot = nslot; nslot = (nslot == 2) ? 0 : nslot + 1;
        if (c == 7) {
            __syncthreads();   // all GEMM reads of Ht for this step complete
            int s = kc >> 3;
            int sx = dir ? (63 - s) : s;
            size_t xzb = ((size_t)(dir*64 + sx)*BATCH + b0)*G3;
#pragma unroll
            for (int i = 0; i < 8; i++) {
                int m = ty*8 + i, b = b0 + m;
                const float* xgp = &d_xg[xzb + (size_t)m*G3];
                float2 xr = *(const float2*)&xgp[j0];
                float2 xz = *(const float2*)&xgp[128 + j0];
                float2 xn = *(const float2*)&xgp[256 + j0];
                float hp0 = Ht[j0][m], hp1 = Ht[j0+1][m];
                float hr0,hr1,hz0,hz1,hn0,hn1;
                UPK2(hr0,hr1,acc[i][0]); UPK2(hz0,hz1,acc[i][1]); UPK2(hn0,hn1,acc[i][2]);
                float r0 = 1.f/(1.f + expf(-(xr.x + hr0 + bhr.x)));
                float r1 = 1.f/(1.f + expf(-(xr.y + hr1 + bhr.y)));
                float z0 = 1.f/(1.f + expf(-(xz.x + hz0 + bhz.x)));
                float z1 = 1.f/(1.f + expf(-(xz.y + hz1 + bhz.y)));
                float n0 = tanhf(xn.x + r0*(hn0 + bhn.x));
                float n1 = tanhf(xn.y + r1*(hn1 + bhn.y));
                float h0 = (1.f - z0)*n0 + z0*hp0;
                float h1 = (1.f - z1)*n1 + z1*hp1;
                Ht[j0][m] = h0; Ht[j0+1][m] = h1;
                *(float2*)&d_go[((size_t)b*64 + sx)*256 + dir*128 + j0] = make_float2(h0, h1);
                acc[i][0] = 0; acc[i][1] = 0; acc[i][2] = 0;
            }
            // next iteration's __syncthreads orders Ht updates before next GEMM
        }
    }
}

// ---------------- w_x = go @ Wx^T: 256x64 tile, f32x2 -------------------------
__global__ __launch_bounds__(256,2) void k_wx() {
    __shared__ __align__(16) float As[32][260];
    __shared__ __align__(16) float Bs[32][68];
    int m0 = blockIdx.x*256;
    int tid = threadIdx.x, ty = tid >> 3, tx = tid & 7;
    u64 acc[8][4] = {};
    for (int kc = 0; kc < 8; kc++) {
        __syncthreads();
#pragma unroll
        for (int p = 0; p < 8; p++) {
            int i = p*256 + tid;
            int m = i >> 3, k4 = (i & 7)*4;
            float4 v = *(const float4*)&d_go[(size_t)(m0+m)*256 + kc*32 + k4];
            As[k4+0][m]=v.x; As[k4+1][m]=v.y; As[k4+2][m]=v.z; As[k4+3][m]=v.w;
        }
        for (int i = tid; i < 32*16; i += 256) {
            int k = i >> 4, n4 = (i & 15)*4;
            *(float4*)&Bs[k][n4] = *(const float4*)&d_wxt[(size_t)(kc*32+k)*64 + n4];
        }
        __syncthreads();
#pragma unroll 4
        for (int k = 0; k < 32; k++) {
            float4 a0 = *(const float4*)&As[k][ty*8];
            float4 a1 = *(const float4*)&As[k][ty*8+4];
            ulonglong2 b0 = *(const ulonglong2*)&Bs[k][tx*8];
            ulonglong2 b1 = *(const ulonglong2*)&Bs[k][tx*8+4];
            ROW8(acc[0], a0.x) ROW8(acc[1], a0.y) ROW8(acc[2], a0.z) ROW8(acc[3], a0.w)
            ROW8(acc[4], a1.x) ROW8(acc[5], a1.y) ROW8(acc[6], a1.z) ROW8(acc[7], a1.w)
        }
    }
#pragma unroll
    for (int i=0;i<8;i++) {
        int m = m0 + ty*8 + i;
        float o[8];
#pragma unroll
        for (int j=0;j<4;j++) UPK2(o[2*j], o[2*j+1], acc[i][j]);
        *(float4*)&d_wx[(size_t)m*64 + tx*8]     = make_float4(o[0],o[1],o[2],o[3]);
        *(float4*)&d_wx[(size_t)m*64 + tx*8 + 4] = make_float4(o[4],o[5],o[6],o[7]);
    }
}

// ---------------- gx[b,c] = sum_s go[b,s,c] * xhat[b,s] -----------------------
__global__ __launch_bounds__(256) void k_gx(const float* __restrict__ x_raw) {
    int b = blockIdx.x;
    int c = threadIdx.x;
    __shared__ float xh[64];
    if (c < 64) xh[c] = 2.f*x_raw[b*64+c] - 3.f;
    __syncthreads();
    float acc = 0.f;
    const float* g = d_go + (size_t)b*64*256;
#pragma unroll 8
    for (int s=0;s<64;s++) acc += g[s*256+c]*xh[s];
    d_gx[(size_t)b*256 + c] = acc;
}

// ---------------- final per-batch: z0, GD loop, output ------------------------
__global__ __launch_bounds__(256) void k_final(const float* __restrict__ Wz,
                                               float* __restrict__ outp) {
    int b = blockIdx.x, tid = threadIdx.x;
    __shared__ float Ws[64][65];
    __shared__ float As[64][65];
    __shared__ float hy[64], zv[64], wh[64], t1[64], t2[64];
    __shared__ float gxs[256];
    for (int i=tid;i<4096;i+=256) Ws[i>>6][i&63] = d_wx[(size_t)b*4096 + i];
    for (int i=tid;i<4096;i+=256) As[i>>6][i&63] = d_HtH[(size_t)b*4096 + i];
    if (tid<64) hy[tid] = d_Hty[b*64+tid];
    gxs[tid] = d_gx[(size_t)b*256 + tid];
    __syncthreads();
    if (tid<64) {
        float a=0.f;
        const float* wz = Wz + tid*256;
#pragma unroll 8
        for (int c=0;c<256;c++) a += wz[c]*gxs[c];
        zv[tid] = a;
        float w=0.f;
#pragma unroll
        for (int s=0;s<64;s++) w += Ws[s][tid]*hy[s];
        wh[tid] = w;
    }
    __syncthreads();
    for (int it=0; it<10; it++) {
        if (tid<64) { float a=0.f;
#pragma unroll
            for (int zc=0;zc<64;zc++) a += Ws[tid][zc]*zv[zc];
            t1[tid]=a; }
        __syncthreads();
        if (tid<64) { float a=0.f;
#pragma unroll
            for (int u=0;u<64;u++) a += As[tid][u]*t1[u];
            t2[tid]=a; }
        __syncthreads();
        if (tid<64) { float a=0.f;
#pragma unroll
            for (int s=0;s<64;s++) a += Ws[s][tid]*t2[s];
            zv[tid] += 2e-6f*(wh[tid]-a); }
        __syncthreads();
    }
    if (tid<64) {
        float a=0.f;
#pragma unroll
        for (int zc=0;zc<64;zc++) a += Ws[tid][zc]*zv[zc];
        outp[b*64+tid] = a;
    }
}

// ---------------- launch -------------------------------------------------------
extern "C" void kernel_launch(void* const* d_in, const int* in_sizes, int n_in,
                              void* d_out, int out_size) {
    const float* y     = (const float*)d_in[0];
    const float* H     = (const float*)d_in[1];
    const float* xraw  = (const float*)d_in[2];
    const float* wih   = (const float*)d_in[3];
    const float* whh   = (const float*)d_in[4];
    const float* bih   = (const float*)d_in[5];
    const float* bhh   = (const float*)d_in[6];
    const float* Wz    = (const float*)d_in[7];
    const float* Wx    = (const float*)d_in[8];
    const float* gamma = (const float*)d_in[9];
    const float* beta  = (const float*)d_in[10];
    float* outp = (float*)d_out;

    cudaFuncSetAttribute(k_xg, cudaFuncAttributeMaxDynamicSharedMemorySize, XG_SMEM);
    cudaFuncSetAttribute(k_gru_all, cudaFuncAttributeMaxDynamicSharedMemorySize, GRUA_SMEM);

    k_init<<<1,256>>>();                                      // slot 0
    k_prep<<<384,256>>>(wih, whh, Wx);                        // slot 1
    k_hth<<<BATCH,256>>>(H, y);                               // slot 2
    k_bn<<<1,768>>>(gamma, beta, wih);                        // slot 3
    k_xg<<<dim3(3,64,128),256,XG_SMEM>>>(bih);                // slot 4
    k_gru_all<<<dim3(256,2),256,GRUA_SMEM>>>(bhh);            // slot 5 (profiled)
    k_wx<<<2048,256>>>();
    k_gx<<<BATCH,256>>>(xraw);
    k_final<<<BATCH,256>>>(Wz, outp);
}

// round 16
// speedup vs baseline: 1.3661x; 1.0321x over previous
#include <cuda_runtime.h>
#include <math.h>

#define BATCH 8192
#define SEQ 64
#define FEAT 65
#define KXG 68
#define HID 128
#define G3 384
#define DZ 64

typedef unsigned long long u64;

// ---------------- packed fp32x2 FMA (FFMA2) ---------------------------------
#define PK2(d, x)       asm("mov.b64 %0, {%1, %1};" : "=l"(d) : "f"(x))
#define FMA2(c, a, b)   asm("fma.rn.f32x2 %0, %1, %2, %0;" : "+l"(c) : "l"(a), "l"(b))
#define UPK2(lo, hi, s) asm("mov.b64 {%0, %1}, %2;" : "=f"(lo), "=f"(hi) : "l"(s))

#define ROW8(acc_i, av)  { u64 aa_; PK2(aa_, av); \
    FMA2(acc_i[0], aa_, b0.x); FMA2(acc_i[1], aa_, b0.y); \
    FMA2(acc_i[2], aa_, b1.x); FMA2(acc_i[3], aa_, b1.y); }

// ---------------- cp.async helpers ------------------------------------------
__device__ __forceinline__ unsigned su32(const void* p) {
    return (unsigned)__cvta_generic_to_shared(p);
}
#define CPA16(dst, src) asm volatile("cp.async.cg.shared.global [%0], [%1], 16;" :: "r"(dst), "l"(src))
#define CPC()           asm volatile("cp.async.commit_group;" ::: "memory")
#define CPW(N)          asm volatile("cp.async.wait_group %0;" :: "n"(N) : "memory")

// ---------------- scratch (device globals; no allocation allowed) ----------
__device__ float  d_HtH[BATCH*64*64];
__device__ float  d_Hty[BATCH*64];
__device__ double d_stats[128];
__device__ float  d_scale[64];
__device__ float  d_shift[64];
__device__ float  d_wsum[2*G3];
__device__ float  d_xg[402653184];               // (2*SEQ*BATCH*G3)
__device__ float  d_go[134217728];               // (BATCH*SEQ*256)
__device__ float  d_wx[BATCH*SEQ*DZ];
__device__ float  d_gx[BATCH*256];
__device__ float  d_wih_t[2*KXG*G3];
__device__ float  d_whh_t[2*HID*G3];
__device__ float  d_wxt[256*DZ];

// ---------------- init -------------------------------------------------------
__global__ __launch_bounds__(256) void k_init() {
    if (blockIdx.x == 0 && threadIdx.x < 128) d_stats[threadIdx.x] = 0.0;
}

// ---------------- weight prep: transpose to k-major --------------------------
__global__ __launch_bounds__(256) void k_prep(const float* __restrict__ wih,
                                              const float* __restrict__ whh,
                                              const float* __restrict__ wx) {
    int idx = blockIdx.x*256 + threadIdx.x;
    if (idx < 2*KXG*G3) {
        int g = idx % G3; int rest = idx / G3;
        int f = rest % KXG; int dir = rest / KXG;
        d_wih_t[idx] = (f < FEAT) ? wih[((size_t)dir*G3 + g)*FEAT + f] : 0.f;
    }
    if (idx < 2*HID*G3) {
        int g = idx % G3; int rest = idx / G3;
        int k = rest % HID; int dir = rest / HID;
        d_whh_t[idx] = whh[((size_t)dir*G3 + g)*HID + k];
    }
    if (idx < 256*DZ) {
        int n = idx & 63, k = idx >> 6;
        d_wxt[idx] = wx[n*256 + k];
    }
}

// ---------------- per-batch HtH, Hty + BN partial stats (f32x2) --------------
__global__ __launch_bounds__(256) void k_hth(const float* __restrict__ Hg,
                                             const float* __restrict__ yg) {
    int b = blockIdx.x;
    __shared__ __align__(16) float Hs[64][68];
    __shared__ float ys[64], hty[64], csum[64], csq[64];
    int tid = threadIdx.x;
    const float* Hb = Hg + (size_t)b*4096;
    for (int i = tid; i < 4096; i += 256) Hs[i>>6][i&63] = Hb[i];
    if (tid < 64) { ys[tid] = yg[b*64+tid]; csum[tid]=0.f; csq[tid]=0.f; }
    __syncthreads();
    if (tid < 64) {
        float a = 0.f;
#pragma unroll
        for (int r=0;r<64;r++) a += Hs[r][tid]*ys[r];
        hty[tid] = a;
        d_Hty[b*64+tid] = a;
    }
    int ty = tid >> 4, tx = tid & 15;
    u64 acc[4][2] = {};
#pragma unroll 8
    for (int r = 0; r < 64; r++) {
        float4 a = *(const float4*)&Hs[r][ty*4];
        ulonglong2 bb = *(const ulonglong2*)&Hs[r][tx*4];
        u64 aa;
        PK2(aa, a.x); FMA2(acc[0][0], aa, bb.x); FMA2(acc[0][1], aa, bb.y);
        PK2(aa, a.y); FMA2(acc[1][0], aa, bb.x); FMA2(acc[1][1], aa, bb.y);
        PK2(aa, a.z); FMA2(acc[2][0], aa, bb.x); FMA2(acc[2][1], aa, bb.y);
        PK2(aa, a.w); FMA2(acc[3][0], aa, bb.x); FMA2(acc[3][1], aa, bb.y);
    }
    float* outp = d_HtH + (size_t)b*4096;
#pragma unroll
    for (int i=0;i<4;i++) {
        float4 v;
        UPK2(v.x, v.y, acc[i][0]);
        UPK2(v.z, v.w, acc[i][1]);
        *reinterpret_cast<float4*>(&outp[(ty*4+i)*64 + tx*4]) = v;
        float s1 = v.x+v.y+v.z+v.w;
        float s2 = v.x*v.x+v.y*v.y+v.z*v.z+v.w*v.w;
        atomicAdd(&csum[ty*4+i], s1);
        atomicAdd(&csq[ty*4+i],  s2);
    }
    __syncthreads();
    if (tid < 64) {
        float v = hty[tid];
        atomicAdd(&d_stats[tid],    (double)(csum[tid]+v));
        atomicAdd(&d_stats[64+tid], (double)(csq[tid]+v*v));
    }
}

// ---------------- finalize BN scale/shift + W_ih row sums --------------------
__global__ void k_bn(const float* __restrict__ gamma, const float* __restrict__ beta,
                     const float* __restrict__ wih) {
    int tid = threadIdx.x;
    if (tid < 64) {
        double n  = (double)BATCH*FEAT;
        double mu = d_stats[tid]/n;
        double var = d_stats[64+tid]/n - mu*mu;
        double sc = (double)gamma[tid] / sqrt(var + 1e-5);
        d_scale[tid] = (float)sc;
        d_shift[tid] = beta[tid] - (float)(mu*sc);
    }
    if (tid < 2*G3) {
        float s = 0.f;
        const float* w = wih + tid*FEAT;
        for (int f=0; f<FEAT; f++) s += w[f];
        d_wsum[tid] = s;
    }
}

// ---------------- GRU input gates: 128x128 tile, cp.async B prefetch ----------
#define XG_SMEM (2*KXG*132*4)
__global__ __launch_bounds__(256,2) void k_xg(const float* __restrict__ bih) {
    extern __shared__ __align__(16) float xs[];
    float (*As)[132] = (float(*)[132])xs;
    float (*Bs)[132] = (float(*)[132])(xs + KXG*132);
    int n0 = blockIdx.x*128, b0 = blockIdx.y*128;
    int z = blockIdx.z, dir = z >> 6, s = z & 63;
    int tid = threadIdx.x;
    // B via cp.async (no register round-trip), overlapped with A transpose fill
    const float* wsrc = d_wih_t + ((size_t)dir*KXG)*G3 + n0;
    for (int i = tid; i < KXG*32; i += 256) {
        int f = i >> 5, n4 = (i & 31)*4;
        CPA16(su32(&Bs[f][n4]), wsrc + (size_t)f*G3 + n4);
    }
    CPC();
    for (int i = tid; i < 128*16; i += 256) {
        int m = i >> 4, f4 = (i & 15)*4;
        float4 v = *(const float4*)&d_HtH[(size_t)(b0+m)*4096 + s*64 + f4];
        As[f4+0][m]=v.x; As[f4+1][m]=v.y; As[f4+2][m]=v.z; As[f4+3][m]=v.w;
    }
    if (tid < 128) {
        As[64][tid] = d_Hty[(b0+tid)*64 + s];
        As[65][tid] = 0.f; As[66][tid] = 0.f; As[67][tid] = 0.f;
    }
    CPW(0);
    __syncthreads();
    int ty = tid >> 4, tx = tid & 15;
    u64 acc[8][4] = {};
#pragma unroll 4
    for (int k = 0; k < KXG; k++) {
        float4 a0 = *(const float4*)&As[k][ty*8];
        float4 a1 = *(const float4*)&As[k][ty*8+4];
        ulonglong2 b0 = *(const ulonglong2*)&Bs[k][tx*8];
        ulonglong2 b1 = *(const ulonglong2*)&Bs[k][tx*8+4];
        ROW8(acc[0], a0.x) ROW8(acc[1], a0.y) ROW8(acc[2], a0.z) ROW8(acc[3], a0.w)
        ROW8(acc[4], a1.x) ROW8(acc[5], a1.y) ROW8(acc[6], a1.z) ROW8(acc[7], a1.w)
    }
    float sc = d_scale[s], sh = d_shift[s];
    int gn = n0 + tx*8;
    float wv[8];
#pragma unroll
    for (int j=0;j<8;j++) wv[j] = sh*d_wsum[dir*G3+gn+j] + bih[dir*G3+gn+j];
    size_t zb = ((size_t)z*BATCH + b0)*G3;
#pragma unroll
    for (int i=0;i<8;i++) {
        int m = ty*8 + i;
        float o[8];
#pragma unroll
        for (int j=0;j<4;j++) {
            float lo, hi; UPK2(lo, hi, acc[i][j]);
            o[2*j]   = lo*sc + wv[2*j];
            o[2*j+1] = hi*sc + wv[2*j+1];
        }
        *(float4*)&d_xg[zb + (size_t)m*G3 + gn]     = make_float4(o[0],o[1],o[2],o[3]);
        *(float4*)&d_xg[zb + (size_t)m*G3 + gn + 4] = make_float4(o[4],o[5],o[6],o[7]);
    }
}

// ---------------- PERSISTENT GRU: all 64 steps, cp.async B ring, h in smem ----
#define CH 16
#define B_CHUNK_BYTES (CH*G3*4)                     // 24576
#define GRUA_SMEM (3*B_CHUNK_BYTES + 128*36*4)      // 92160
__global__ __launch_bounds__(256,2) void k_gru_all(const float* __restrict__ bhh) {
    extern __shared__ __align__(16) char gsm[];
    float (*Bs)[CH][G3] = (float(*)[CH][G3])gsm;          // [3][16][384]
    float (*Ht)[36]     = (float(*)[36])(gsm + 3*B_CHUNK_BYTES);  // [k=128][m=32]
    int dir = blockIdx.y, b0 = blockIdx.x*32;
    int tid = threadIdx.x, ty = tid >> 6, tx = tid & 63;
    const float* wt = d_whh_t + (size_t)dir*HID*G3;
    for (int i = tid; i < 128*36; i += 256) ((float*)Ht)[i] = 0.f;
#pragma unroll
    for (int p = 0; p < 6; p++) {
        int i = p*256 + tid;
        int k = i / 96, n4 = (i - k*96)*4;
        CPA16(su32(&Bs[0][k][n4]), wt + (size_t)k*G3 + n4);
    }
    CPC();

    int j0 = tx*2;
    const float* bh = bhh + dir*G3;
    float2 bhr = *(const float2*)&bh[j0];
    float2 bhz = *(const float2*)&bh[128 + j0];
    float2 bhn = *(const float2*)&bh[256 + j0];
    u64 acc[8][3] = {};
    int slot = 0, nslot = 1;

    for (int kc = 0; kc < 512; kc++) {
        if (kc + 1 < 512) {
            int nc = (kc + 1) & 7;
#pragma unroll
            for (int p = 0; p < 6; p++) {
                int i = p*256 + tid;
                int k = i / 96, n4 = (i - k*96)*4;
                CPA16(su32(&Bs[nslot][k][n4]), wt + (size_t)(nc*CH + k)*G3 + n4);
            }
            CPC();
            CPW(1);
        } else {
            CPW(0);
        }
        __syncthreads();
        int c = kc & 7;
#pragma unroll 8
        for (int k = 0; k < CH; k++) {
            int kg = c*CH + k;
            float4 a0 = *(const float4*)&Ht[kg][ty*8];
            float4 a1 = *(const float4*)&Ht[kg][ty*8+4];
            u64 br = *(const u64*)&Bs[slot][k][j0];
            u64 bz = *(const u64*)&Bs[slot][k][128 + j0];
            u64 bn = *(const u64*)&Bs[slot][k][256 + j0];
            u64 aa;
            PK2(aa, a0.x); FMA2(acc[0][0], aa, br); FMA2(acc[0][1], aa, bz); FMA2(acc[0][2], aa, bn);
            PK2(aa, a0.y); FMA2(acc[1][0], aa, br); FMA2(acc[1][1], aa, bz); FMA2(acc[1][2], aa, bn);
            PK2(aa, a0.z); FMA2(acc[2][0], aa, br); FMA2(acc[2][1], aa, bz); FMA2(acc[2][2], aa, bn);
            PK2(aa, a0.w); FMA2(acc[3][0], aa, br); FMA2(acc[3][1], aa, bz); FMA2(acc[3][2], aa, bn);
            PK2(aa, a1.x); FMA2(acc[4][0], aa, br); FMA2(acc[4][1], aa, bz); FMA2(acc[4][2], aa, bn);
            PK2(aa, a1.y); FMA2(acc[5][0], aa, br); FMA2(acc[5][1], aa, bz); FMA2(acc[5][2], aa, bn);
            PK2(aa, a1.z); FMA2(acc[6][0], aa, br); FMA2(acc[6][1], aa, bz); FMA2(acc[6][2], aa, bn);
            PK2(aa, a1.w); FMA2(acc[7][0], aa, br); FMA2(acc[7][1], aa, bz); FMA2(acc[7][2], aa, bn);
        }
        slot = nslot; nslot = (nslot == 2) ? 0 : nslot + 1;
        if (c == 7) {
            __syncthreads();
            int s = kc >> 3;
            int sx = dir ? (63 - s) : s;
            size_t xzb = ((size_t)(dir*64 + sx)*BATCH + b0)*G3;
#pragma unroll
            for (int i = 0; i < 8; i++) {
                int m = ty*8 + i, b = b0 + m;
                const float* xgp = &d_xg[xzb + (size_t)m*G3];
                float2 xr = *(const float2*)&xgp[j0];
                float2 xz = *(const float2*)&xgp[128 + j0];
                float2 xn = *(const float2*)&xgp[256 + j0];
                float hp0 = Ht[j0][m], hp1 = Ht[j0+1][m];
                float hr0,hr1,hz0,hz1,hn0,hn1;
                UPK2(hr0,hr1,acc[i][0]); UPK2(hz0,hz1,acc[i][1]); UPK2(hn0,hn1,acc[i][2]);
                float r0 = 1.f/(1.f + expf(-(xr.x + hr0 + bhr.x)));
                float r1 = 1.f/(1.f + expf(-(xr.y + hr1 + bhr.y)));
                float z0 = 1.f/(1.f + expf(-(xz.x + hz0 + bhz.x)));
                float z1 = 1.f/(1.f + expf(-(xz.y + hz1 + bhz.y)));
                float n0 = tanhf(xn.x + r0*(hn0 + bhn.x));
                float n1 = tanhf(xn.y + r1*(hn1 + bhn.y));
                float h0 = (1.f - z0)*n0 + z0*hp0;
                float h1 = (1.f - z1)*n1 + z1*hp1;
                Ht[j0][m] = h0; Ht[j0+1][m] = h1;
                *(float2*)&d_go[((size_t)b*64 + sx)*256 + dir*128 + j0] = make_float2(h0, h1);
                acc[i][0] = 0; acc[i][1] = 0; acc[i][2] = 0;
            }
        }
    }
}

// ---------------- w_x = go @ Wx^T + fused gx ----------------------------------
__global__ __launch_bounds__(256,2) void k_wx(const float* __restrict__ x_raw) {
    __shared__ __align__(16) float As[32][260];
    __shared__ __align__(16) float Bs[32][68];
    __shared__ float xh[4][64];
    int m0 = blockIdx.x*256;
    int bb = blockIdx.x*4;           // 4 batches per block
    int tid = threadIdx.x, ty = tid >> 3, tx = tid & 7;
    xh[tid>>6][tid&63] = 2.f*x_raw[(size_t)(bb + (tid>>6))*64 + (tid&63)] - 3.f;
    u64 acc[8][4] = {};
    for (int kc = 0; kc < 8; kc++) {
        __syncthreads();
#pragma unroll
        for (int p = 0; p < 8; p++) {
            int i = p*256 + tid;
            int m = i >> 3, k4 = (i & 7)*4;
            float4 v = *(const float4*)&d_go[(size_t)(m0+m)*256 + kc*32 + k4];
            As[k4+0][m]=v.x; As[k4+1][m]=v.y; As[k4+2][m]=v.z; As[k4+3][m]=v.w;
        }
        for (int i = tid; i < 32*16; i += 256) {
            int k = i >> 4, n4 = (i & 15)*4;
            *(float4*)&Bs[k][n4] = *(const float4*)&d_wxt[(size_t)(kc*32+k)*64 + n4];
        }
        __syncthreads();
        if (tid < 128) {   // gx: 4 batches x 32 c, full 64-s reduction from As
            int bl = tid >> 5, cc = tid & 31;
            float a = 0.f;
#pragma unroll 8
            for (int s = 0; s < 64; s++) a += As[cc][bl*64 + s]*xh[bl][s];
            d_gx[(size_t)(bb + bl)*256 + kc*32 + cc] = a;
        }
#pragma unroll 4
        for (int k = 0; k < 32; k++) {
            float4 a0 = *(const float4*)&As[k][ty*8];
            float4 a1 = *(const float4*)&As[k][ty*8+4];
            ulonglong2 b0 = *(const ulonglong2*)&Bs[k][tx*8];
            ulonglong2 b1 = *(const ulonglong2*)&Bs[k][tx*8+4];
            ROW8(acc[0], a0.x) ROW8(acc[1], a0.y) ROW8(acc[2], a0.z) ROW8(acc[3], a0.w)
            ROW8(acc[4], a1.x) ROW8(acc[5], a1.y) ROW8(acc[6], a1.z) ROW8(acc[7], a1.w)
        }
    }
#pragma unroll
    for (int i=0;i<8;i++) {
        int m = m0 + ty*8 + i;
        float o[8];
#pragma unroll
        for (int j=0;j<4;j++) UPK2(o[2*j], o[2*j+1], acc[i][j]);
        *(float4*)&d_wx[(size_t)m*64 + tx*8]     = make_float4(o[0],o[1],o[2],o[3]);
        *(float4*)&d_wx[(size_t)m*64 + tx*8 + 4] = make_float4(o[4],o[5],o[6],o[7]);
    }
}

// ---------------- final per-batch: z0, GD loop, output ------------------------
__global__ __launch_bounds__(256) void k_final(const float* __restrict__ Wz,
                                               float* __restrict__ outp) {
    int b = blockIdx.x, tid = threadIdx.x;
    __shared__ float Ws[64][65];
    __shared__ float As[64][65];
    __shared__ float hy[64], zv[64], wh[64], t1[64], t2[64];
    __shared__ float gxs[256];
    for (int i=tid;i<4096;i+=256) Ws[i>>6][i&63] = d_wx[(size_t)b*4096 + i];
    for (int i=tid;i<4096;i+=256) As[i>>6][i&63] = d_HtH[(size_t)b*4096 + i];
    if (tid<64) hy[tid] = d_Hty[b*64+tid];
    gxs[tid] = d_gx[(size_t)b*256 + tid];
    __syncthreads();
    if (tid<64) {
        float a=0.f;
        const float* wz = Wz + tid*256;
#pragma unroll 8
        for (int c=0;c<256;c++) a += wz[c]*gxs[c];
        zv[tid] = a;
        float w=0.f;
#pragma unroll
        for (int s=0;s<64;s++) w += Ws[s][tid]*hy[s];
        wh[tid] = w;
    }
    __syncthreads();
    for (int it=0; it<10; it++) {
        if (tid<64) { float a=0.f;
#pragma unroll
            for (int zc=0;zc<64;zc++) a += Ws[tid][zc]*zv[zc];
            t1[tid]=a; }
        __syncthreads();
        if (tid<64) { float a=0.f;
#pragma unroll
            for (int u=0;u<64;u++) a += As[tid][u]*t1[u];
            t2[tid]=a; }
        __syncthreads();
        if (tid<64) { float a=0.f;
#pragma unroll
            for (int s=0;s<64;s++) a += Ws[s][tid]*t2[s];
            zv[tid] += 2e-6f*(wh[tid]-a); }
        __syncthreads();
    }
    if (tid<64) {
        float a=0.f;
#pragma unroll
        for (int zc=0;zc<64;zc++) a += Ws[tid][zc]*zv[zc];
        outp[b*64+tid] = a;
    }
}

// ---------------- launch -------------------------------------------------------
extern "C" void kernel_launch(void* const* d_in, const int* in_sizes, int n_in,
                              void* d_out, int out_size) {
    const float* y     = (const float*)d_in[0];
    const float* H     = (const float*)d_in[1];
    const float* xraw  = (const float*)d_in[2];
    const float* wih   = (const float*)d_in[3];
    const float* whh   = (const float*)d_in[4];
    const float* bih   = (const float*)d_in[5];
    const float* bhh   = (const float*)d_in[6];
    const float* Wz    = (const float*)d_in[7];
    const float* Wx    = (const float*)d_in[8];
    const float* gamma = (const float*)d_in[9];
    const float* beta  = (const float*)d_in[10];
    float* outp = (float*)d_out;

    cudaFuncSetAttribute(k_xg, cudaFuncAttributeMaxDynamicSharedMemorySize, XG_SMEM);
    cudaFuncSetAttribute(k_gru_all, cudaFuncAttributeMaxDynamicSharedMemorySize, GRUA_SMEM);

    k_init<<<1,256>>>();
    k_prep<<<384,256>>>(wih, whh, Wx);
    k_hth<<<BATCH,256>>>(H, y);
    k_bn<<<1,768>>>(gamma, beta, wih);
    k_xg<<<dim3(3,64,128),256,XG_SMEM>>>(bih);
    k_gru_all<<<dim3(256,2),256,GRUA_SMEM>>>(bhh);
    k_wx<<<2048,256>>>(xraw);
    k_final<<<BATCH,256>>>(Wz, outp);
}

// round 17
// speedup vs baseline: 1.4319x; 1.0481x over previous
#include <cuda_runtime.h>
#include <math.h>

#define BATCH 8192
#define SEQ 64
#define FEAT 65
#define KXG 68
#define HID 128
#define G3 384
#define DZ 64

typedef unsigned long long u64;

// ---------------- packed fp32x2 FMA (FFMA2) ---------------------------------
#define PK2(d, x)       asm("mov.b64 %0, {%1, %1};" : "=l"(d) : "f"(x))
#define FMA2(c, a, b)   asm("fma.rn.f32x2 %0, %1, %2, %0;" : "+l"(c) : "l"(a), "l"(b))
#define UPK2(lo, hi, s) asm("mov.b64 {%0, %1}, %2;" : "=f"(lo), "=f"(hi) : "l"(s))

#define ROW8(acc_i, av)  { u64 aa_; PK2(aa_, av); \
    FMA2(acc_i[0], aa_, b0.x); FMA2(acc_i[1], aa_, b0.y); \
    FMA2(acc_i[2], aa_, b1.x); FMA2(acc_i[3], aa_, b1.y); }

// ---------------- cp.async helpers ------------------------------------------
__device__ __forceinline__ unsigned su32(const void* p) {
    return (unsigned)__cvta_generic_to_shared(p);
}
#define CPA16(dst, src) asm volatile("cp.async.cg.shared.global [%0], [%1], 16;" :: "r"(dst), "l"(src))
#define CPC()           asm volatile("cp.async.commit_group;" ::: "memory")
#define CPW(N)          asm volatile("cp.async.wait_group %0;" :: "n"(N) : "memory")

// ---------------- scratch (device globals; no allocation allowed) ----------
__device__ float  d_HtH[BATCH*64*64];
__device__ float  d_Hty[BATCH*64];
__device__ double d_stats[128];
__device__ float  d_scale[64];
__device__ float  d_shift[64];
__device__ float  d_wsum[2*G3];
__device__ float  d_ft[SEQ*KXG*BATCH];           // feats transposed [s][f][b] 142 MB
__device__ float  d_xg[402653184];               // (2*SEQ*BATCH*G3)
__device__ float  d_go[134217728];               // (BATCH*SEQ*256)
__device__ float  d_wx[BATCH*SEQ*DZ];
__device__ float  d_gx[BATCH*256];
__device__ float  d_wih_t[2*KXG*G3];
__device__ float  d_whh_t[2*HID*G3];
__device__ float  d_wxt[256*DZ];

// ---------------- init -------------------------------------------------------
__global__ __launch_bounds__(256) void k_init() {
    if (blockIdx.x == 0 && threadIdx.x < 128) d_stats[threadIdx.x] = 0.0;
}

// ---------------- weight prep: transpose to k-major --------------------------
__global__ __launch_bounds__(256) void k_prep(const float* __restrict__ wih,
                                              const float* __restrict__ whh,
                                              const float* __restrict__ wx) {
    int idx = blockIdx.x*256 + threadIdx.x;
    if (idx < 2*KXG*G3) {
        int g = idx % G3; int rest = idx / G3;
        int f = rest % KXG; int dir = rest / KXG;
        d_wih_t[idx] = (f < FEAT) ? wih[((size_t)dir*G3 + g)*FEAT + f] : 0.f;
    }
    if (idx < 2*HID*G3) {
        int g = idx % G3; int rest = idx / G3;
        int k = rest % HID; int dir = rest / HID;
        d_whh_t[idx] = whh[((size_t)dir*G3 + g)*HID + k];
    }
    if (idx < 256*DZ) {
        int n = idx & 63, k = idx >> 6;
        d_wxt[idx] = wx[n*256 + k];
    }
}

// ---------------- per-batch HtH, Hty + BN partial stats (f32x2) --------------
__global__ __launch_bounds__(256) void k_hth(const float* __restrict__ Hg,
                                             const float* __restrict__ yg) {
    int b = blockIdx.x;
    __shared__ __align__(16) float Hs[64][68];
    __shared__ float ys[64], hty[64], csum[64], csq[64];
    int tid = threadIdx.x;
    const float* Hb = Hg + (size_t)b*4096;
    for (int i = tid; i < 4096; i += 256) Hs[i>>6][i&63] = Hb[i];
    if (tid < 64) { ys[tid] = yg[b*64+tid]; csum[tid]=0.f; csq[tid]=0.f; }
    __syncthreads();
    if (tid < 64) {
        float a = 0.f;
#pragma unroll
        for (int r=0;r<64;r++) a += Hs[r][tid]*ys[r];
        hty[tid] = a;
        d_Hty[b*64+tid] = a;
    }
    int ty = tid >> 4, tx = tid & 15;
    u64 acc[4][2] = {};
#pragma unroll 8
    for (int r = 0; r < 64; r++) {
        float4 a = *(const float4*)&Hs[r][ty*4];
        ulonglong2 bb = *(const ulonglong2*)&Hs[r][tx*4];
        u64 aa;
        PK2(aa, a.x); FMA2(acc[0][0], aa, bb.x); FMA2(acc[0][1], aa, bb.y);
        PK2(aa, a.y); FMA2(acc[1][0], aa, bb.x); FMA2(acc[1][1], aa, bb.y);
        PK2(aa, a.z); FMA2(acc[2][0], aa, bb.x); FMA2(acc[2][1], aa, bb.y);
        PK2(aa, a.w); FMA2(acc[3][0], aa, bb.x); FMA2(acc[3][1], aa, bb.y);
    }
    float* outp = d_HtH + (size_t)b*4096;
#pragma unroll
    for (int i=0;i<4;i++) {
        float4 v;
        UPK2(v.x, v.y, acc[i][0]);
        UPK2(v.z, v.w, acc[i][1]);
        *reinterpret_cast<float4*>(&outp[(ty*4+i)*64 + tx*4]) = v;
        float s1 = v.x+v.y+v.z+v.w;
        float s2 = v.x*v.x+v.y*v.y+v.z*v.z+v.w*v.w;
        atomicAdd(&csum[ty*4+i], s1);
        atomicAdd(&csq[ty*4+i],  s2);
    }
    __syncthreads();
    if (tid < 64) {
        float v = hty[tid];
        atomicAdd(&d_stats[tid],    (double)(csum[tid]+v));
        atomicAdd(&d_stats[64+tid], (double)(csq[tid]+v*v));
    }
}

// ---------------- feats transpose: d_ft[s][f][b] ------------------------------
__global__ __launch_bounds__(256) void k_tr() {
    __shared__ __align__(16) float T[KXG][132];
    int s = blockIdx.x, bt = blockIdx.y;      // b-tile of 128
    int tid = threadIdx.x;
    int b0 = bt*128;
    for (int i = tid; i < 128*16; i += 256) {
        int m = i >> 4, f4 = (i & 15)*4;
        float4 v = *(const float4*)&d_HtH[(size_t)(b0+m)*4096 + s*64 + f4];
        T[f4+0][m]=v.x; T[f4+1][m]=v.y; T[f4+2][m]=v.z; T[f4+3][m]=v.w;
    }
    if (tid < 128) {
        T[64][tid] = d_Hty[(b0+tid)*64 + s];
        T[65][tid] = 0.f; T[66][tid] = 0.f; T[67][tid] = 0.f;
    }
    __syncthreads();
    float* dst = d_ft + (size_t)s*KXG*BATCH + b0;
    for (int i = tid; i < KXG*32; i += 256) {
        int f = i >> 5, m4 = (i & 31)*4;
        *(float4*)&dst[(size_t)f*BATCH + m4] = *(const float4*)&T[f][m4];
    }
}

// ---------------- finalize BN scale/shift + W_ih row sums --------------------
__global__ void k_bn(const float* __restrict__ gamma, const float* __restrict__ beta,
                     const float* __restrict__ wih) {
    int tid = threadIdx.x;
    if (tid < 64) {
        double n  = (double)BATCH*FEAT;
        double mu = d_stats[tid]/n;
        double var = d_stats[64+tid]/n - mu*mu;
        double sc = (double)gamma[tid] / sqrt(var + 1e-5);
        d_scale[tid] = (float)sc;
        d_shift[tid] = beta[tid] - (float)(mu*sc);
    }
    if (tid < 2*G3) {
        float s = 0.f;
        const float* w = wih + tid*FEAT;
        for (int f=0; f<FEAT; f++) s += w[f];
        d_wsum[tid] = s;
    }
}

// ---------------- GRU input gates: fully cp.async fills -----------------------
#define XG_SMEM (2*KXG*132*4)
__global__ __launch_bounds__(256,2) void k_xg(const float* __restrict__ bih) {
    extern __shared__ __align__(16) float xs[];
    float (*As)[132] = (float(*)[132])xs;
    float (*Bs)[132] = (float(*)[132])(xs + KXG*132);
    int n0 = blockIdx.x*128, b0 = blockIdx.y*128;
    int z = blockIdx.z, dir = z >> 6, s = z & 63;
    int tid = threadIdx.x;
    // A via cp.async from transposed feats (contiguous rows)
    const float* fsrc = d_ft + (size_t)s*KXG*BATCH + b0;
    for (int i = tid; i < KXG*32; i += 256) {
        int f = i >> 5, m4 = (i & 31)*4;
        CPA16(su32(&As[f][m4]), fsrc + (size_t)f*BATCH + m4);
    }
    // B via cp.async
    const float* wsrc = d_wih_t + ((size_t)dir*KXG)*G3 + n0;
    for (int i = tid; i < KXG*32; i += 256) {
        int f = i >> 5, n4 = (i & 31)*4;
        CPA16(su32(&Bs[f][n4]), wsrc + (size_t)f*G3 + n4);
    }
    CPC();
    CPW(0);
    __syncthreads();
    int ty = tid >> 4, tx = tid & 15;
    u64 acc[8][4] = {};
#pragma unroll 4
    for (int k = 0; k < KXG; k++) {
        float4 a0 = *(const float4*)&As[k][ty*8];
        float4 a1 = *(const float4*)&As[k][ty*8+4];
        ulonglong2 b0 = *(const ulonglong2*)&Bs[k][tx*8];
        ulonglong2 b1 = *(const ulonglong2*)&Bs[k][tx*8+4];
        ROW8(acc[0], a0.x) ROW8(acc[1], a0.y) ROW8(acc[2], a0.z) ROW8(acc[3], a0.w)
        ROW8(acc[4], a1.x) ROW8(acc[5], a1.y) ROW8(acc[6], a1.z) ROW8(acc[7], a1.w)
    }
    float sc = d_scale[s], sh = d_shift[s];
    int gn = n0 + tx*8;
    float wv[8];
#pragma unroll
    for (int j=0;j<8;j++) wv[j] = sh*d_wsum[dir*G3+gn+j] + bih[dir*G3+gn+j];
    size_t zb = ((size_t)z*BATCH + b0)*G3;
#pragma unroll
    for (int i=0;i<8;i++) {
        int m = ty*8 + i;
        float o[8];
#pragma unroll
        for (int j=0;j<4;j++) {
            float lo, hi; UPK2(lo, hi, acc[i][j]);
            o[2*j]   = lo*sc + wv[2*j];
            o[2*j+1] = hi*sc + wv[2*j+1];
        }
        *(float4*)&d_xg[zb + (size_t)m*G3 + gn]     = make_float4(o[0],o[1],o[2],o[3]);
        *(float4*)&d_xg[zb + (size_t)m*G3 + gn + 4] = make_float4(o[4],o[5],o[6],o[7]);
    }
}

// ---------------- PERSISTENT GRU: all 64 steps, cp.async B ring, h in smem ----
#define CH 16
#define B_CHUNK_BYTES (CH*G3*4)                     // 24576
#define GRUA_SMEM (3*B_CHUNK_BYTES + 128*36*4)      // 92160
__global__ __launch_bounds__(256,2) void k_gru_all(const float* __restrict__ bhh) {
    extern __shared__ __align__(16) char gsm[];
    float (*Bs)[CH][G3] = (float(*)[CH][G3])gsm;          // [3][16][384]
    float (*Ht)[36]     = (float(*)[36])(gsm + 3*B_CHUNK_BYTES);  // [k=128][m=32]
    int dir = blockIdx.y, b0 = blockIdx.x*32;
    int tid = threadIdx.x, ty = tid >> 6, tx = tid & 63;
    const float* wt = d_whh_t + (size_t)dir*HID*G3;
    for (int i = tid; i < 128*36; i += 256) ((float*)Ht)[i] = 0.f;
#pragma unroll
    for (int p = 0; p < 6; p++) {
        int i = p*256 + tid;
        int k = i / 96, n4 = (i - k*96)*4;
        CPA16(su32(&Bs[0][k][n4]), wt + (size_t)k*G3 + n4);
    }
    CPC();

    int j0 = tx*2;
    const float* bh = bhh + dir*G3;
    float2 bhr = *(const float2*)&bh[j0];
    float2 bhz = *(const float2*)&bh[128 + j0];
    float2 bhn = *(const float2*)&bh[256 + j0];
    u64 acc[8][3] = {};
    int slot = 0, nslot = 1;

    for (int kc = 0; kc < 512; kc++) {
        if (kc + 1 < 512) {
            int nc = (kc + 1) & 7;
#pragma unroll
            for (int p = 0; p < 6; p++) {
                int i = p*256 + tid;
                int k = i / 96, n4 = (i - k*96)*4;
                CPA16(su32(&Bs[nslot][k][n4]), wt + (size_t)(nc*CH + k)*G3 + n4);
            }
            CPC();
            CPW(1);
        } else {
            CPW(0);
        }
        __syncthreads();
        int c = kc & 7;
#pragma unroll 8
        for (int k = 0; k < CH; k++) {
            int kg = c*CH + k;
            float4 a0 = *(const float4*)&Ht[kg][ty*8];
            float4 a1 = *(const float4*)&Ht[kg][ty*8+4];
            u64 br = *(const u64*)&Bs[slot][k][j0];
            u64 bz = *(const u64*)&Bs[slot][k][128 + j0];
            u64 bn = *(const u64*)&Bs[slot][k][256 + j0];
            u64 aa;
            PK2(aa, a0.x); FMA2(acc[0][0], aa, br); FMA2(acc[0][1], aa, bz); FMA2(acc[0][2], aa, bn);
            PK2(aa, a0.y); FMA2(acc[1][0], aa, br); FMA2(acc[1][1], aa, bz); FMA2(acc[1][2], aa, bn);
            PK2(aa, a0.z); FMA2(acc[2][0], aa, br); FMA2(acc[2][1], aa, bz); FMA2(acc[2][2], aa, bn);
            PK2(aa, a0.w); FMA2(acc[3][0], aa, br); FMA2(acc[3][1], aa, bz); FMA2(acc[3][2], aa, bn);
            PK2(aa, a1.x); FMA2(acc[4][0], aa, br); FMA2(acc[4][1], aa, bz); FMA2(acc[4][2], aa, bn);
            PK2(aa, a1.y); FMA2(acc[5][0], aa, br); FMA2(acc[5][1], aa, bz); FMA2(acc[5][2], aa, bn);
            PK2(aa, a1.z); FMA2(acc[6][0], aa, br); FMA2(acc[6][1], aa, bz); FMA2(acc[6][2], aa, bn);
            PK2(aa, a1.w); FMA2(acc[7][0], aa, br); FMA2(acc[7][1], aa, bz); FMA2(acc[7][2], aa, bn);
        }
        slot = nslot; nslot = (nslot == 2) ? 0 : nslot + 1;
        if (c == 7) {
            __syncthreads();
            int s = kc >> 3;
            int sx = dir ? (63 - s) : s;
            size_t xzb = ((size_t)(dir*64 + sx)*BATCH + b0)*G3;
#pragma unroll
            for (int i = 0; i < 8; i++) {
                int m = ty*8 + i, b = b0 + m;
                const float* xgp = &d_xg[xzb + (size_t)m*G3];
                float2 xr = *(const float2*)&xgp[j0];
                float2 xz = *(const float2*)&xgp[128 + j0];
                float2 xn = *(const float2*)&xgp[256 + j0];
                float hp0 = Ht[j0][m], hp1 = Ht[j0+1][m];
                float hr0,hr1,hz0,hz1,hn0,hn1;
                UPK2(hr0,hr1,acc[i][0]); UPK2(hz0,hz1,acc[i][1]); UPK2(hn0,hn1,acc[i][2]);
                float r0 = 1.f/(1.f + expf(-(xr.x + hr0 + bhr.x)));
                float r1 = 1.f/(1.f + expf(-(xr.y + hr1 + bhr.y)));
                float z0 = 1.f/(1.f + expf(-(xz.x + hz0 + bhz.x)));
                float z1 = 1.f/(1.f + expf(-(xz.y + hz1 + bhz.y)));
                float n0 = tanhf(xn.x + r0*(hn0 + bhn.x));
                float n1 = tanhf(xn.y + r1*(hn1 + bhn.y));
                float h0 = (1.f - z0)*n0 + z0*hp0;
                float h1 = (1.f - z1)*n1 + z1*hp1;
                Ht[j0][m] = h0; Ht[j0+1][m] = h1;
                *(float2*)&d_go[((size_t)b*64 + sx)*256 + dir*128 + j0] = make_float2(h0, h1);
                acc[i][0] = 0; acc[i][1] = 0; acc[i][2] = 0;
            }
        }
    }
}

// ---------------- w_x = go @ Wx^T + fused gx ----------------------------------
__global__ __launch_bounds__(256,2) void k_wx(const float* __restrict__ x_raw) {
    __shared__ __align__(16) float As[32][260];
    __shared__ __align__(16) float Bs[32][68];
    __shared__ float xh[4][64];
    int m0 = blockIdx.x*256;
    int bb = blockIdx.x*4;           // 4 batches per block
    int tid = threadIdx.x, ty = tid >> 3, tx = tid & 7;
    xh[tid>>6][tid&63] = 2.f*x_raw[(size_t)(bb + (tid>>6))*64 + (tid&63)] - 3.f;
    u64 acc[8][4] = {};
    for (int kc = 0; kc < 8; kc++) {
        __syncthreads();
#pragma unroll
        for (int p = 0; p < 8; p++) {
            int i = p*256 + tid;
            int m = i >> 3, k4 = (i & 7)*4;
            float4 v = *(const float4*)&d_go[(size_t)(m0+m)*256 + kc*32 + k4];
            As[k4+0][m]=v.x; As[k4+1][m]=v.y; As[k4+2][m]=v.z; As[k4+3][m]=v.w;
        }
        for (int i = tid; i < 32*16; i += 256) {
            int k = i >> 4, n4 = (i & 15)*4;
            *(float4*)&Bs[k][n4] = *(const float4*)&d_wxt[(size_t)(kc*32+k)*64 + n4];
        }
        __syncthreads();
        if (tid < 128) {   // gx: 4 batches x 32 c, full 64-s reduction from As
            int bl = tid >> 5, cc = tid & 31;
            float a = 0.f;
#pragma unroll 8
            for (int s = 0; s < 64; s++) a += As[cc][bl*64 + s]*xh[bl][s];
            d_gx[(size_t)(bb + bl)*256 + kc*32 + cc] = a;
        }
#pragma unroll 4
        for (int k = 0; k < 32; k++) {
            float4 a0 = *(const float4*)&As[k][ty*8];
            float4 a1 = *(const float4*)&As[k][ty*8+4];
            ulonglong2 b0 = *(const ulonglong2*)&Bs[k][tx*8];
            ulonglong2 b1 = *(const ulonglong2*)&Bs[k][tx*8+4];
            ROW8(acc[0], a0.x) ROW8(acc[1], a0.y) ROW8(acc[2], a0.z) ROW8(acc[3], a0.w)
            ROW8(acc[4], a1.x) ROW8(acc[5], a1.y) ROW8(acc[6], a1.z) ROW8(acc[7], a1.w)
        }
    }
#pragma unroll
    for (int i=0;i<8;i++) {
        int m = m0 + ty*8 + i;
        float o[8];
#pragma unroll
        for (int j=0;j<4;j++) UPK2(o[2*j], o[2*j+1], acc[i][j]);
        *(float4*)&d_wx[(size_t)m*64 + tx*8]     = make_float4(o[0],o[1],o[2],o[3]);
        *(float4*)&d_wx[(size_t)m*64 + tx*8 + 4] = make_float4(o[4],o[5],o[6],o[7]);
    }
}

// ---------------- final per-batch: z0, GD loop, output ------------------------
__global__ __launch_bounds__(256) void k_final(const float* __restrict__ Wz,
                                               float* __restrict__ outp) {
    int b = blockIdx.x, tid = threadIdx.x;
    __shared__ float Ws[64][65];
    __shared__ float As[64][65];
    __shared__ float hy[64], zv[64], wh[64], t1[64], t2[64];
    __shared__ float gxs[256];
    for (int i=tid;i<4096;i+=256) Ws[i>>6][i&63] = d_wx[(size_t)b*4096 + i];
    for (int i=tid;i<4096;i+=256) As[i>>6][i&63] = d_HtH[(size_t)b*4096 + i];
    if (tid<64) hy[tid] = d_Hty[b*64+tid];
    gxs[tid] = d_gx[(size_t)b*256 + tid];
    __syncthreads();
    if (tid<64) {
        float a=0.f;
        const float* wz = Wz + tid*256;
#pragma unroll 8
        for (int c=0;c<256;c++) a += wz[c]*gxs[c];
        zv[tid] = a;
        float w=0.f;
#pragma unroll
        for (int s=0;s<64;s++) w += Ws[s][tid]*hy[s];
        wh[tid] = w;
    }
    __syncthreads();
    for (int it=0; it<10; it++) {
        if (tid<64) { float a=0.f;
#pragma unroll
            for (int zc=0;zc<64;zc++) a += Ws[tid][zc]*zv[zc];
            t1[tid]=a; }
        __syncthreads();
        if (tid<64) { float a=0.f;
#pragma unroll
            for (int u=0;u<64;u++) a += As[tid][u]*t1[u];
            t2[tid]=a; }
        __syncthreads();
        if (tid<64) { float a=0.f;
#pragma unroll
            for (int s=0;s<64;s++) a += Ws[s][tid]*t2[s];
            zv[tid] += 2e-6f*(wh[tid]-a); }
        __syncthreads();
    }
    if (tid<64) {
        float a=0.f;
#pragma unroll
        for (int zc=0;zc<64;zc++) a += Ws[tid][zc]*zv[zc];
        outp[b*64+tid] = a;
    }
}

// ---------------- launch -------------------------------------------------------
extern "C" void kernel_launch(void* const* d_in, const int* in_sizes, int n_in,
                              void* d_out, int out_size) {
    const float* y     = (const float*)d_in[0];
    const float* H     = (const float*)d_in[1];
    const float* xraw  = (const float*)d_in[2];
    const float* wih   = (const float*)d_in[3];
    const float* whh   = (const float*)d_in[4];
    const float* bih   = (const float*)d_in[5];
    const float* bhh   = (const float*)d_in[6];
    const float* Wz    = (const float*)d_in[7];
    const float* Wx    = (const float*)d_in[8];
    const float* gamma = (const float*)d_in[9];
    const float* beta  = (const float*)d_in[10];
    float* outp = (float*)d_out;

    cudaFuncSetAttribute(k_xg, cudaFuncAttributeMaxDynamicSharedMemorySize, XG_SMEM);
    cudaFuncSetAttribute(k_gru_all, cudaFuncAttributeMaxDynamicSharedMemorySize, GRUA_SMEM);

    k_init<<<1,256>>>();
    k_prep<<<384,256>>>(wih, whh, Wx);
    k_hth<<<BATCH,256>>>(H, y);
    k_tr<<<dim3(64,64),256>>>();
    k_bn<<<1,768>>>(gamma, beta, wih);
    k_xg<<<dim3(3,64,128),256,XG_SMEM>>>(bih);
    k_gru_all<<<dim3(256,2),256,GRUA_SMEM>>>(bhh);
    k_wx<<<2048,256>>>(xraw);
    k_final<<<BATCH,256>>>(Wz, outp);
}